// round 11
// baseline (speedup 1.0000x reference)
#include <cuda_runtime.h>
#include <math.h>

// ---------------- problem constants ----------------
#define BATCH 64
#define NTOK  320
#define NT    64
#define NS    256
#define DIM   768
#define NH    12
#define HD    64
#define MLPH  3072
#define NKEEP 180
#define NREM  76
#define NOUT  244
#define M1    (BATCH*NTOK)   // 20480
#define M2    (BATCH*NOUT)   // 15616

// output layout (flat float32)
#define OFF_XRGB 0LL
#define OFF_XTIR 11993088LL
#define OFF_GT   23986176LL
#define OFF_GS   23990272LL
#define OFF_RM   24001792LL
#define OFF_CR   24006656LL
#define OFF_CT   102649856LL

// ---------------- device scratch ----------------
__device__ float g_ln[(size_t)M1*DIM];
__device__ float g_q [(size_t)BATCH*NH*NTOK*HD];
__device__ float g_k [(size_t)BATCH*NH*NTOK*HD];
__device__ float g_v [(size_t)BATCH*NH*NTOK*HD];
__device__ float g_av[(size_t)M1*DIM];
__device__ float g_xres0[(size_t)M1*DIM];
__device__ float g_xres1[(size_t)M1*DIM];
__device__ float g_h [(size_t)M2*MLPH];
__device__ float g_score[BATCH*NS];
__device__ int   g_topk[BATCH*NKEEP];

// ---------------- reductions ----------------
__device__ __forceinline__ float block_sum(float v, float* red) {
    #pragma unroll
    for (int o = 16; o > 0; o >>= 1) v += __shfl_xor_sync(0xffffffffu, v, o);
    int tid = threadIdx.x;
    if ((tid & 31) == 0) red[tid >> 5] = v;
    __syncthreads();
    if (tid < 32) {
        float t = (tid < 8) ? red[tid] : 0.f;
        #pragma unroll
        for (int o = 4; o > 0; o >>= 1) t += __shfl_xor_sync(0xffffffffu, t, o);
        if (tid == 0) red[0] = t;
    }
    __syncthreads();
    float r = red[0];
    __syncthreads();
    return r;
}

// ---------------- LayerNorm (row = token of 768), block tree ----------------
__global__ void ln_kernel(const float* __restrict__ in, float* __restrict__ out,
                          const float* __restrict__ gam, const float* __restrict__ bet) {
    __shared__ float red[32];
    size_t row = blockIdx.x;
    const float* x = in + row * DIM;
    float* o = out + row * DIM;
    int tid = threadIdx.x;           // 256
    float lv[3];
    float s = 0.f;
    #pragma unroll
    for (int i = 0; i < 3; i++) { lv[i] = x[tid + i*256]; s += lv[i]; }
    float mean = block_sum(s, red) * (1.0f / DIM);
    float vs = 0.f;
    #pragma unroll
    for (int i = 0; i < 3; i++) { float d = lv[i] - mean; vs += d * d; }
    float var = block_sum(vs, red) * (1.0f / DIM);
    float rstd = rsqrtf(var + 1e-5f);
    #pragma unroll
    for (int i = 0; i < 3; i++) {
        int c = tid + i*256;
        o[c] = (lv[i] - mean) * rstd * gam[c] + bet[c];
    }
}

// ---------------- generic SGEMM 128x128x8, 8x8/thread ----------------
#define EPI_QKV  0
#define EPI_RES  1
#define EPI_GELU 2
#define EPI_ADD  3

__global__ void __launch_bounds__(256) sgemm_kernel(
    const float* __restrict__ A, const float* __restrict__ W,
    const float* __restrict__ bias, int M, int N, int K, int mode,
    float* __restrict__ out, const float* __restrict__ aux,
    float* __restrict__ qp, float* __restrict__ kp, float* __restrict__ vp) {

    __shared__ float As[8][128];
    __shared__ float Bs[8][128];
    int tid = threadIdx.x;
    int bm = blockIdx.y * 128, bn = blockIdx.x * 128;
    int ty = tid >> 4, tx = tid & 15;

    float acc[8][8];
    #pragma unroll
    for (int i = 0; i < 8; i++)
        #pragma unroll
        for (int j = 0; j < 8; j++) acc[i][j] = 0.f;

    int arow = tid >> 1, acol = (tid & 1) * 4;
    int brow = tid >> 5, bcol = (tid & 31) * 4;
    const float* Aptr = A + (size_t)(bm + arow) * K + acol;
    const float* Wptr = W + (size_t)brow * N + bn + bcol;

    for (int k0 = 0; k0 < K; k0 += 8) {
        float4 a = *(const float4*)(Aptr + k0);
        As[acol+0][arow] = a.x; As[acol+1][arow] = a.y;
        As[acol+2][arow] = a.z; As[acol+3][arow] = a.w;
        *(float4*)&Bs[brow][bcol] = *(const float4*)(Wptr + (size_t)k0 * N);
        __syncthreads();
        #pragma unroll
        for (int kk = 0; kk < 8; kk++) {
            float ra[8], rb[8];
            #pragma unroll
            for (int i = 0; i < 8; i++) ra[i] = As[kk][ty*8 + i];
            #pragma unroll
            for (int j = 0; j < 8; j++) rb[j] = Bs[kk][tx*8 + j];
            #pragma unroll
            for (int i = 0; i < 8; i++)
                #pragma unroll
                for (int j = 0; j < 8; j++)
                    acc[i][j] = fmaf(ra[i], rb[j], acc[i][j]);
        }
        __syncthreads();
    }

    #pragma unroll
    for (int i = 0; i < 8; i++) {
        int r = bm + ty*8 + i;
        #pragma unroll
        for (int j = 0; j < 8; j++) {
            int c = bn + tx*8 + j;
            float val = acc[i][j] + bias[c];
            if (mode == EPI_QKV) {
                int which = c / 768;
                int h = (c % 768) >> 6;
                int d = c & 63;
                int b = r / NTOK, n = r % NTOK;
                size_t dst = (((size_t)(b*NH + h)) * NTOK + n) * HD + d;
                float* base = (which == 0) ? qp : (which == 1) ? kp : vp;
                base[dst] = val;
            } else if (mode == EPI_RES) {
                size_t idx = (size_t)r * N + c;
                out[idx] = val + aux[idx];
            } else if (mode == EPI_GELU) {
                out[(size_t)r * N + c] = val * normcdff(val);
            } else { // EPI_ADD
                size_t idx = (size_t)r * N + c;
                out[idx] += val;
            }
        }
    }
}

// ---------------- attention: logits tile 32x32 (K=64) ----------------
__global__ void __launch_bounds__(256) logits_kernel(
    const float* __restrict__ q, const float* __restrict__ k, float* __restrict__ corr) {
    __shared__ float qs[32][65];
    __shared__ float ks[32][65];
    int tid = threadIdx.x;
    int bh = blockIdx.z;
    int m0 = blockIdx.y * 32, n0 = blockIdx.x * 32;
    const float* qb = q + ((size_t)bh * NTOK + m0) * HD;
    const float* kb = k + ((size_t)bh * NTOK + n0) * HD;
    for (int i = tid; i < 32*64; i += 256) {
        int r = i >> 6, c = i & 63;
        qs[r][c] = qb[(size_t)r * HD + c];
        ks[r][c] = kb[(size_t)r * HD + c];
    }
    __syncthreads();
    int ty = tid >> 5, tx = tid & 31;
    float acc0 = 0.f, acc1 = 0.f, acc2 = 0.f, acc3 = 0.f;
    #pragma unroll
    for (int d = 0; d < 64; d++) {
        float kv = ks[tx][d];
        acc0 = fmaf(qs[ty     ][d], kv, acc0);
        acc1 = fmaf(qs[ty + 8 ][d], kv, acc1);
        acc2 = fmaf(qs[ty + 16][d], kv, acc2);
        acc3 = fmaf(qs[ty + 24][d], kv, acc3);
    }
    float* cb = corr + ((size_t)bh * NTOK + m0) * NTOK + n0;
    cb[(size_t)(ty     ) * NTOK + tx] = acc0 * 0.125f;
    cb[(size_t)(ty + 8 ) * NTOK + tx] = acc1 * 0.125f;
    cb[(size_t)(ty + 16) * NTOK + tx] = acc2 * 0.125f;
    cb[(size_t)(ty + 24) * NTOK + tx] = acc3 * 0.125f;
}

// ---------------- softmax: warp per row, vec2 lanes ----------------
__global__ void __launch_bounds__(256) softmax_kernel(float* __restrict__ p) {
    int gwarp = (blockIdx.x * blockDim.x + threadIdx.x) >> 5;
    int lane = threadIdx.x & 31;
    float* x = p + (size_t)gwarp * NTOK;

    float v[10];
    #pragma unroll
    for (int i = 0; i < 5; i++) {
        v[2*i]   = x[64*i + 2*lane];
        v[2*i+1] = x[64*i + 2*lane + 1];
    }
    float m = v[0];
    #pragma unroll
    for (int j = 1; j < 10; j++) m = fmaxf(m, v[j]);
    #pragma unroll
    for (int o = 16; o > 0; o >>= 1)
        m = fmaxf(m, __shfl_down_sync(0xffffffffu, m, o));
    m = __shfl_sync(0xffffffffu, m, 0);

    float e[10];
    float a0 = 0.f, a1 = 0.f;
    #pragma unroll
    for (int i = 0; i < 5; i++) {
        e[2*i]   = expf(__fsub_rn(v[2*i],   m));
        e[2*i+1] = expf(__fsub_rn(v[2*i+1], m));
        a0 = __fadd_rn(a0, e[2*i]);
        a1 = __fadd_rn(a1, e[2*i+1]);
    }
    float S = __fadd_rn(a0, a1);
    #pragma unroll
    for (int o = 16; o > 0; o >>= 1)
        S = __fadd_rn(S, __shfl_down_sync(0xffffffffu, S, o));
    S = __shfl_sync(0xffffffffu, S, 0);

    #pragma unroll
    for (int i = 0; i < 5; i++) {
        x[64*i + 2*lane]     = __fdiv_rn(e[2*i],   S);
        x[64*i + 2*lane + 1] = __fdiv_rn(e[2*i+1], S);
    }
}

// ---------------- attention: O = P @ V (tile 32 rows x 64 cols) ----------------
__global__ void __launch_bounds__(256) av_kernel(
    const float* __restrict__ corr, const float* __restrict__ v, float* __restrict__ av) {
    __shared__ float Ps[32][33];
    __shared__ float Vs[32][65];
    int tid = threadIdx.x;
    int bh = blockIdx.y;
    int m0 = blockIdx.x * 32;
    int b = bh / NH, h = bh % NH;
    int ty = tid >> 6, tx = tid & 63;   // ty in [0,4)
    float acc[8];
    #pragma unroll
    for (int i = 0; i < 8; i++) acc[i] = 0.f;

    for (int k0 = 0; k0 < NTOK; k0 += 32) {
        for (int i = tid; i < 32*32; i += 256) {
            int r = i >> 5, c = i & 31;
            Ps[r][c] = corr[((size_t)bh * NTOK + m0 + r) * NTOK + k0 + c];
        }
        for (int i = tid; i < 32*64; i += 256) {
            int r = i >> 6, c = i & 63;
            Vs[r][c] = v[((size_t)bh * NTOK + k0 + r) * HD + c];
        }
        __syncthreads();
        #pragma unroll
        for (int kk = 0; kk < 32; kk++) {
            float vv = Vs[kk][tx];
            #pragma unroll
            for (int r8 = 0; r8 < 8; r8++)
                acc[r8] = fmaf(Ps[ty + 4*r8][kk], vv, acc[r8]);
        }
        __syncthreads();
    }
    #pragma unroll
    for (int r8 = 0; r8 < 8; r8++) {
        int n = m0 + ty + 4*r8;
        av[(((size_t)(b*NTOK + n)) * NH + h) * HD + tx] = acc[r8];
    }
}

// ---------------- saliency score: contig-24 chain + tree, recip-mul mean ----
// One warp per (b, s). Lane t sequentially accumulates e[i] = cr[i]+ct[i] over
// the CONTIGUOUS chunk i in [24*t, 24*t+24) (i = h*64+q row-major), then the
// shfl_down binary tree (16,8,4,2,1), then mean via MULTIPLY by fp32(1/768)
// (jnp.mean lowering: sum * reciprocal-constant, not divide).
__global__ void score_kernel(const float* __restrict__ cr, const float* __restrict__ ct) {
    int gwarp = (blockIdx.x * blockDim.x + threadIdx.x) >> 5;  // 0 .. BATCH*NS-1
    int lane = threadIdx.x & 31;
    int b = gwarp >> 8;        // / NS
    int s = gwarp & 255;       // % NS
    float acc = 0.f;
    int i0 = lane * 24;
    #pragma unroll 4
    for (int j = 0; j < 24; j++) {
        int i = i0 + j;                   // i = h*64 + q, contiguous per lane
        int h = i >> 6, q = i & 63;
        size_t off = (((size_t)(b*NH + h)) * NTOK + q) * NTOK + NT + s;
        float e = __fadd_rn(cr[off], ct[off]);  // fp32 elementwise add
        acc = __fadd_rn(acc, e);                // sequential chain
    }
    #pragma unroll
    for (int o = 16; o > 0; o >>= 1)
        acc = __fadd_rn(acc, __shfl_down_sync(0xffffffffu, acc, o));
    if (lane == 0) g_score[b*NS + s] = __fmul_rn(acc, (1.0f / 768.0f));
}

// ---------------- stable descending argsort (bitonic 256, fp32 keys) ----------------
__global__ void sort_kernel(const int* __restrict__ gidx_s,
                            float* __restrict__ out_gs, float* __restrict__ out_rm) {
    __shared__ float sk[256];
    __shared__ int   si[256];
    int b = blockIdx.x, tid = threadIdx.x;
    sk[tid] = g_score[b*NS + tid];
    si[tid] = tid;
    __syncthreads();
    for (int k = 2; k <= 256; k <<= 1) {
        for (int j = k >> 1; j > 0; j >>= 1) {
            int ixj = tid ^ j;
            if (ixj > tid) {
                float ka = sk[tid], kb = sk[ixj];
                int ia = si[tid], ib = si[ixj];
                bool before = (ka > kb) || (ka == kb && ia < ib);
                bool up = ((tid & k) == 0);
                if (up ? !before : before) {
                    sk[tid] = kb; sk[ixj] = ka;
                    si[tid] = ib; si[ixj] = ia;
                }
            }
            __syncthreads();
        }
    }
    int idx = si[tid];
    float gv = (float)gidx_s[b*NS + idx];
    if (tid < NKEEP) {
        out_gs[b*NKEEP + tid] = gv;
        g_topk[b*NKEEP + tid] = idx;
    } else {
        out_rm[b*NREM + (tid - NKEEP)] = gv;
    }
}

// ---------------- copy global_index_t (int -> float) ----------------
__global__ void copy_gt_kernel(const int* __restrict__ gt, float* __restrict__ o) {
    int i = blockIdx.x * 256 + threadIdx.x;
    if (i < BATCH * NT) o[i] = (float)gt[i];
}

// ---------------- token gather (apply keep) ----------------
__global__ void gather_kernel(const float* __restrict__ xres, float* __restrict__ outx) {
    int bt = blockIdx.x;
    int b = bt / NOUT, t = bt % NOUT;
    int src = (t < NT) ? t : NT + g_topk[b*NKEEP + (t - NT)];
    const float* s = xres + ((size_t)(b*NTOK + src)) * DIM;
    float* d = outx + (size_t)bt * DIM;
    for (int c = threadIdx.x; c < DIM; c += 256) d[c] = s[c];
}

// ---------------- launcher ----------------
extern "C" void kernel_launch(void* const* d_in, const int* in_sizes, int n_in,
                              void* d_out, int out_size) {
    const float* x_rgb = (const float*)d_in[0];
    const float* x_tir = (const float*)d_in[1];
    const int*   gt    = (const int*)  d_in[2];
    const int*   gs    = (const int*)  d_in[3];
    const float* n1g = (const float*)d_in[4],  *n1b = (const float*)d_in[5];
    const float* qkvw= (const float*)d_in[6],  *qkvb= (const float*)d_in[7];
    const float* projw=(const float*)d_in[8],  *projb=(const float*)d_in[9];
    const float* n2g = (const float*)d_in[10], *n2b = (const float*)d_in[11];
    const float* fc1w= (const float*)d_in[12], *fc1b= (const float*)d_in[13];
    const float* fc2w= (const float*)d_in[14], *fc2b= (const float*)d_in[15];
    float* out = (float*)d_out;

    float *ln, *q, *k, *v, *av, *xr0, *xr1, *hbuf;
    cudaGetSymbolAddress((void**)&ln,   g_ln);
    cudaGetSymbolAddress((void**)&q,    g_q);
    cudaGetSymbolAddress((void**)&k,    g_k);
    cudaGetSymbolAddress((void**)&v,    g_v);
    cudaGetSymbolAddress((void**)&av,   g_av);
    cudaGetSymbolAddress((void**)&xr0,  g_xres0);
    cudaGetSymbolAddress((void**)&xr1,  g_xres1);
    cudaGetSymbolAddress((void**)&hbuf, g_h);

    float* corr[2]       = { out + OFF_CR, out + OFF_CT };
    const float* xin[2]  = { x_rgb, x_tir };
    float* xres[2]       = { xr0, xr1 };
    float* xout[2]       = { out + OFF_XRGB, out + OFF_XTIR };

    for (int m = 0; m < 2; m++) {
        ln_kernel<<<M1, 256>>>(xin[m], ln, n1g, n1b);
        sgemm_kernel<<<dim3(2304/128, M1/128), 256>>>(
            ln, qkvw, qkvb, M1, 2304, DIM, EPI_QKV, nullptr, nullptr, q, k, v);
        logits_kernel<<<dim3(NTOK/32, NTOK/32, BATCH*NH), 256>>>(q, k, corr[m]);
        softmax_kernel<<<(BATCH*NH*NTOK)/8, 256>>>(corr[m]);
        av_kernel<<<dim3(NTOK/32, BATCH*NH), 256>>>(corr[m], v, av);
        sgemm_kernel<<<dim3(DIM/128, M1/128), 256>>>(
            av, projw, projb, M1, DIM, DIM, EPI_RES, xres[m], xin[m],
            nullptr, nullptr, nullptr);
    }

    score_kernel<<<(BATCH*NS*32)/256, 256>>>(corr[0], corr[1]);
    sort_kernel<<<BATCH, 256>>>(gs, out + OFF_GS, out + OFF_RM);
    copy_gt_kernel<<<(BATCH*NT + 255)/256, 256>>>(gt, out + OFF_GT);

    for (int m = 0; m < 2; m++)
        gather_kernel<<<BATCH*NOUT, 256>>>(xres[m], xout[m]);

    for (int m = 0; m < 2; m++) {
        ln_kernel<<<M2, 256>>>(xout[m], ln, n2g, n2b);
        sgemm_kernel<<<dim3(MLPH/128, M2/128), 256>>>(
            ln, fc1w, fc1b, M2, MLPH, DIM, EPI_GELU, hbuf, nullptr,
            nullptr, nullptr, nullptr);
        sgemm_kernel<<<dim3(DIM/128, M2/128), 256>>>(
            hbuf, fc2w, fc2b, M2, DIM, MLPH, EPI_ADD, xout[m], nullptr,
            nullptr, nullptr, nullptr);
    }
}

// round 12
// speedup vs baseline: 1.6510x; 1.6510x over previous
#include <cuda_runtime.h>
#include <math.h>
#include <stdint.h>

// ---------------- problem constants ----------------
#define BATCH 64
#define NTOK  320
#define NT    64
#define NS    256
#define DIM   768
#define NH    12
#define HD    64
#define MLPH  3072
#define NKEEP 180
#define NREM  76
#define NOUT  244
#define M1    (BATCH*NTOK)   // 20480
#define M2    (BATCH*NOUT)   // 15616

// output layout (flat float32)
#define OFF_XRGB 0LL
#define OFF_XTIR 11993088LL
#define OFF_GT   23986176LL
#define OFF_GS   23990272LL
#define OFF_RM   24001792LL
#define OFF_CR   24006656LL
#define OFF_CT   102649856LL

// ---------------- device scratch ----------------
__device__ float g_ln[(size_t)M1*DIM];
__device__ float g_q [(size_t)BATCH*NH*NTOK*HD];
__device__ float g_k [(size_t)BATCH*NH*NTOK*HD];
__device__ float g_v [(size_t)BATCH*NH*NTOK*HD];
__device__ float g_av[(size_t)M1*DIM];
__device__ float g_xres0[(size_t)M1*DIM];
__device__ float g_xres1[(size_t)M1*DIM];
__device__ float g_h [(size_t)M2*MLPH];
__device__ float g_score[BATCH*NS];
__device__ int   g_topk[BATCH*NKEEP];

// ---------------- reductions ----------------
__device__ __forceinline__ float block_sum(float v, float* red) {
    #pragma unroll
    for (int o = 16; o > 0; o >>= 1) v += __shfl_xor_sync(0xffffffffu, v, o);
    int tid = threadIdx.x;
    if ((tid & 31) == 0) red[tid >> 5] = v;
    __syncthreads();
    if (tid < 32) {
        float t = (tid < 8) ? red[tid] : 0.f;
        #pragma unroll
        for (int o = 4; o > 0; o >>= 1) t += __shfl_xor_sync(0xffffffffu, t, o);
        if (tid == 0) red[0] = t;
    }
    __syncthreads();
    float r = red[0];
    __syncthreads();
    return r;
}

// ---------------- LayerNorm (row = token of 768), block tree ----------------
__global__ void ln_kernel(const float* __restrict__ in, float* __restrict__ out,
                          const float* __restrict__ gam, const float* __restrict__ bet) {
    __shared__ float red[32];
    size_t row = blockIdx.x;
    const float* x = in + row * DIM;
    float* o = out + row * DIM;
    int tid = threadIdx.x;           // 256
    float lv[3];
    float s = 0.f;
    #pragma unroll
    for (int i = 0; i < 3; i++) { lv[i] = x[tid + i*256]; s += lv[i]; }
    float mean = block_sum(s, red) * (1.0f / DIM);
    float vs = 0.f;
    #pragma unroll
    for (int i = 0; i < 3; i++) { float d = lv[i] - mean; vs += d * d; }
    float var = block_sum(vs, red) * (1.0f / DIM);
    float rstd = rsqrtf(var + 1e-5f);
    #pragma unroll
    for (int i = 0; i < 3; i++) {
        int c = tid + i*256;
        o[c] = (lv[i] - mean) * rstd * gam[c] + bet[c];
    }
}

// ---------------- exact fp32 SGEMM (QKV only: feeds the ranking path) -------
#define EPI_QKV  0

__global__ void __launch_bounds__(256) sgemm_kernel(
    const float* __restrict__ A, const float* __restrict__ W,
    const float* __restrict__ bias, int M, int N, int K, int mode,
    float* __restrict__ out, const float* __restrict__ aux,
    float* __restrict__ qp, float* __restrict__ kp, float* __restrict__ vp) {

    __shared__ float As[8][128];
    __shared__ float Bs[8][128];
    int tid = threadIdx.x;
    int bm = blockIdx.y * 128, bn = blockIdx.x * 128;
    int ty = tid >> 4, tx = tid & 15;

    float acc[8][8];
    #pragma unroll
    for (int i = 0; i < 8; i++)
        #pragma unroll
        for (int j = 0; j < 8; j++) acc[i][j] = 0.f;

    int arow = tid >> 1, acol = (tid & 1) * 4;
    int brow = tid >> 5, bcol = (tid & 31) * 4;
    const float* Aptr = A + (size_t)(bm + arow) * K + acol;
    const float* Wptr = W + (size_t)brow * N + bn + bcol;

    for (int k0 = 0; k0 < K; k0 += 8) {
        float4 a = *(const float4*)(Aptr + k0);
        As[acol+0][arow] = a.x; As[acol+1][arow] = a.y;
        As[acol+2][arow] = a.z; As[acol+3][arow] = a.w;
        *(float4*)&Bs[brow][bcol] = *(const float4*)(Wptr + (size_t)k0 * N);
        __syncthreads();
        #pragma unroll
        for (int kk = 0; kk < 8; kk++) {
            float ra[8], rb[8];
            #pragma unroll
            for (int i = 0; i < 8; i++) ra[i] = As[kk][ty*8 + i];
            #pragma unroll
            for (int j = 0; j < 8; j++) rb[j] = Bs[kk][tx*8 + j];
            #pragma unroll
            for (int i = 0; i < 8; i++)
                #pragma unroll
                for (int j = 0; j < 8; j++)
                    acc[i][j] = fmaf(ra[i], rb[j], acc[i][j]);
        }
        __syncthreads();
    }

    #pragma unroll
    for (int i = 0; i < 8; i++) {
        int r = bm + ty*8 + i;
        #pragma unroll
        for (int j = 0; j < 8; j++) {
            int c = bn + tx*8 + j;
            float val = acc[i][j] + bias[c];
            // EPI_QKV scatter
            int which = c / 768;
            int h = (c % 768) >> 6;
            int d = c & 63;
            int b = r / NTOK, n = r % NTOK;
            size_t dst = (((size_t)(b*NH + h)) * NTOK + n) * HD + d;
            float* base = (which == 0) ? qp : (which == 1) ? kp : vp;
            base[dst] = val;
        }
    }
}

// ---------------- TF32 tensor-core GEMM (proj / fc1 / fc2) ------------------
#define TEPI_RES  1
#define TEPI_GELU 2
#define TEPI_ADD  3
#define SPAD 8

__device__ __forceinline__ uint32_t f2tf32(float f) {
    uint32_t r;
    asm("cvt.rna.tf32.f32 %0, %1;" : "=r"(r) : "f"(f));
    return r;
}

__device__ __forceinline__ void mma_tf32(float* c, const uint32_t* a, const uint32_t* b) {
    asm volatile(
        "mma.sync.aligned.m16n8k8.row.col.f32.tf32.tf32.f32 "
        "{%0,%1,%2,%3}, {%4,%5,%6,%7}, {%8,%9}, {%0,%1,%2,%3};"
        : "+f"(c[0]), "+f"(c[1]), "+f"(c[2]), "+f"(c[3])
        : "r"(a[0]), "r"(a[1]), "r"(a[2]), "r"(a[3]), "r"(b[0]), "r"(b[1]));
}

__global__ void __launch_bounds__(256) tf32gemm_kernel(
    const float* __restrict__ A, const float* __restrict__ W,
    const float* __restrict__ bias, int M, int N, int K, int mode,
    float* __restrict__ out, const float* __restrict__ aux) {

    __shared__ uint32_t As[16][128 + SPAD];
    __shared__ uint32_t Bs[16][128 + SPAD];

    int tid = threadIdx.x;
    int bm = blockIdx.y * 128, bn = blockIdx.x * 128;
    int warp = tid >> 5, lane = tid & 31;
    int g = lane >> 2, ctg = lane & 3;
    int wr = (warp >> 2) * 64;   // 0 / 64
    int wc = (warp & 3) * 32;    // 0,32,64,96

    float acc[4][4][4];
    #pragma unroll
    for (int mt = 0; mt < 4; mt++)
        #pragma unroll
        for (int nt = 0; nt < 4; nt++)
            #pragma unroll
            for (int r = 0; r < 4; r++) acc[mt][nt][r] = 0.f;

    int arow = tid >> 1, acol0 = (tid & 1) * 8;
    int brow = tid >> 4, bcol0 = (tid & 15) * 8;
    const float* Ap = A + (size_t)(bm + arow) * K;
    const float* Wp = W + bn;

    for (int k0 = 0; k0 < K; k0 += 16) {
        float4 av0 = *(const float4*)(Ap + k0 + acol0);
        float4 av1 = *(const float4*)(Ap + k0 + acol0 + 4);
        As[acol0+0][arow] = f2tf32(av0.x); As[acol0+1][arow] = f2tf32(av0.y);
        As[acol0+2][arow] = f2tf32(av0.z); As[acol0+3][arow] = f2tf32(av0.w);
        As[acol0+4][arow] = f2tf32(av1.x); As[acol0+5][arow] = f2tf32(av1.y);
        As[acol0+6][arow] = f2tf32(av1.z); As[acol0+7][arow] = f2tf32(av1.w);

        const float* wrow = Wp + (size_t)(k0 + brow) * N + bcol0;
        float4 bv0 = *(const float4*)(wrow);
        float4 bv1 = *(const float4*)(wrow + 4);
        uint4 bu0, bu1;
        bu0.x = f2tf32(bv0.x); bu0.y = f2tf32(bv0.y);
        bu0.z = f2tf32(bv0.z); bu0.w = f2tf32(bv0.w);
        bu1.x = f2tf32(bv1.x); bu1.y = f2tf32(bv1.y);
        bu1.z = f2tf32(bv1.z); bu1.w = f2tf32(bv1.w);
        *(uint4*)&Bs[brow][bcol0]     = bu0;
        *(uint4*)&Bs[brow][bcol0 + 4] = bu1;
        __syncthreads();

        #pragma unroll
        for (int ks = 0; ks < 16; ks += 8) {
            uint32_t af[4][4];
            #pragma unroll
            for (int mt = 0; mt < 4; mt++) {
                int m0 = wr + mt*16 + g;
                af[mt][0] = As[ks+ctg  ][m0];
                af[mt][1] = As[ks+ctg  ][m0+8];
                af[mt][2] = As[ks+ctg+4][m0];
                af[mt][3] = As[ks+ctg+4][m0+8];
            }
            uint32_t bf[4][2];
            #pragma unroll
            for (int nt = 0; nt < 4; nt++) {
                int n0 = wc + nt*8 + g;
                bf[nt][0] = Bs[ks+ctg  ][n0];
                bf[nt][1] = Bs[ks+ctg+4][n0];
            }
            #pragma unroll
            for (int mt = 0; mt < 4; mt++)
                #pragma unroll
                for (int nt = 0; nt < 4; nt++)
                    mma_tf32(acc[mt][nt], af[mt], bf[nt]);
        }
        __syncthreads();
    }

    #pragma unroll
    for (int mt = 0; mt < 4; mt++) {
        #pragma unroll
        for (int nt = 0; nt < 4; nt++) {
            int r0 = bm + wr + mt*16 + g;
            int c0 = bn + wc + nt*8 + ctg*2;
            #pragma unroll
            for (int rr = 0; rr < 2; rr++) {      // row 0 / +8
                int r = r0 + rr*8;
                #pragma unroll
                for (int cc = 0; cc < 2; cc++) {  // col 0 / +1
                    int c = c0 + cc;
                    float val = acc[mt][nt][rr*2 + cc] + bias[c];
                    size_t idx = (size_t)r * N + c;
                    if (mode == TEPI_RES)       out[idx] = val + aux[idx];
                    else if (mode == TEPI_GELU) out[idx] = val * normcdff(val);
                    else                        out[idx] += val;   // TEPI_ADD
                }
            }
        }
    }
}

// ---------------- attention: logits tile 32x32 (K=64) ----------------
__global__ void __launch_bounds__(256) logits_kernel(
    const float* __restrict__ q, const float* __restrict__ k, float* __restrict__ corr) {
    __shared__ float qs[32][65];
    __shared__ float ks[32][65];
    int tid = threadIdx.x;
    int bh = blockIdx.z;
    int m0 = blockIdx.y * 32, n0 = blockIdx.x * 32;
    const float* qb = q + ((size_t)bh * NTOK + m0) * HD;
    const float* kb = k + ((size_t)bh * NTOK + n0) * HD;
    for (int i = tid; i < 32*64; i += 256) {
        int r = i >> 6, c = i & 63;
        qs[r][c] = qb[(size_t)r * HD + c];
        ks[r][c] = kb[(size_t)r * HD + c];
    }
    __syncthreads();
    int ty = tid >> 5, tx = tid & 31;
    float acc0 = 0.f, acc1 = 0.f, acc2 = 0.f, acc3 = 0.f;
    #pragma unroll
    for (int d = 0; d < 64; d++) {
        float kv = ks[tx][d];
        acc0 = fmaf(qs[ty     ][d], kv, acc0);
        acc1 = fmaf(qs[ty + 8 ][d], kv, acc1);
        acc2 = fmaf(qs[ty + 16][d], kv, acc2);
        acc3 = fmaf(qs[ty + 24][d], kv, acc3);
    }
    float* cb = corr + ((size_t)bh * NTOK + m0) * NTOK + n0;
    cb[(size_t)(ty     ) * NTOK + tx] = acc0 * 0.125f;
    cb[(size_t)(ty + 8 ) * NTOK + tx] = acc1 * 0.125f;
    cb[(size_t)(ty + 16) * NTOK + tx] = acc2 * 0.125f;
    cb[(size_t)(ty + 24) * NTOK + tx] = acc3 * 0.125f;
}

// ---------------- softmax: warp per row, vec2 lanes ----------------
__global__ void __launch_bounds__(256) softmax_kernel(float* __restrict__ p) {
    int gwarp = (blockIdx.x * blockDim.x + threadIdx.x) >> 5;
    int lane = threadIdx.x & 31;
    float* x = p + (size_t)gwarp * NTOK;

    float v[10];
    #pragma unroll
    for (int i = 0; i < 5; i++) {
        v[2*i]   = x[64*i + 2*lane];
        v[2*i+1] = x[64*i + 2*lane + 1];
    }
    float m = v[0];
    #pragma unroll
    for (int j = 1; j < 10; j++) m = fmaxf(m, v[j]);
    #pragma unroll
    for (int o = 16; o > 0; o >>= 1)
        m = fmaxf(m, __shfl_down_sync(0xffffffffu, m, o));
    m = __shfl_sync(0xffffffffu, m, 0);

    float e[10];
    float a0 = 0.f, a1 = 0.f;
    #pragma unroll
    for (int i = 0; i < 5; i++) {
        e[2*i]   = expf(__fsub_rn(v[2*i],   m));
        e[2*i+1] = expf(__fsub_rn(v[2*i+1], m));
        a0 = __fadd_rn(a0, e[2*i]);
        a1 = __fadd_rn(a1, e[2*i+1]);
    }
    float S = __fadd_rn(a0, a1);
    #pragma unroll
    for (int o = 16; o > 0; o >>= 1)
        S = __fadd_rn(S, __shfl_down_sync(0xffffffffu, S, o));
    S = __shfl_sync(0xffffffffu, S, 0);

    #pragma unroll
    for (int i = 0; i < 5; i++) {
        x[64*i + 2*lane]     = __fdiv_rn(e[2*i],   S);
        x[64*i + 2*lane + 1] = __fdiv_rn(e[2*i+1], S);
    }
}

// ---------------- attention: O = P @ V (tile 32 rows x 64 cols) ----------------
__global__ void __launch_bounds__(256) av_kernel(
    const float* __restrict__ corr, const float* __restrict__ v, float* __restrict__ av) {
    __shared__ float Ps[32][33];
    __shared__ float Vs[32][65];
    int tid = threadIdx.x;
    int bh = blockIdx.y;
    int m0 = blockIdx.x * 32;
    int b = bh / NH, h = bh % NH;
    int ty = tid >> 6, tx = tid & 63;   // ty in [0,4)
    float acc[8];
    #pragma unroll
    for (int i = 0; i < 8; i++) acc[i] = 0.f;

    for (int k0 = 0; k0 < NTOK; k0 += 32) {
        for (int i = tid; i < 32*32; i += 256) {
            int r = i >> 5, c = i & 31;
            Ps[r][c] = corr[((size_t)bh * NTOK + m0 + r) * NTOK + k0 + c];
        }
        for (int i = tid; i < 32*64; i += 256) {
            int r = i >> 6, c = i & 63;
            Vs[r][c] = v[((size_t)bh * NTOK + k0 + r) * HD + c];
        }
        __syncthreads();
        #pragma unroll
        for (int kk = 0; kk < 32; kk++) {
            float vv = Vs[kk][tx];
            #pragma unroll
            for (int r8 = 0; r8 < 8; r8++)
                acc[r8] = fmaf(Ps[ty + 4*r8][kk], vv, acc[r8]);
        }
        __syncthreads();
    }
    #pragma unroll
    for (int r8 = 0; r8 < 8; r8++) {
        int n = m0 + ty + 4*r8;
        av[(((size_t)(b*NTOK + n)) * NH + h) * HD + tx] = acc[r8];
    }
}

// ---------------- proj residual done via TF32 kernel; av is its A input -----

// ---------------- saliency score: contig-24 chain + tree, recip-mul mean ----
__global__ void score_kernel(const float* __restrict__ cr, const float* __restrict__ ct) {
    int gwarp = (blockIdx.x * blockDim.x + threadIdx.x) >> 5;  // 0 .. BATCH*NS-1
    int lane = threadIdx.x & 31;
    int b = gwarp >> 8;        // / NS
    int s = gwarp & 255;       // % NS
    float acc = 0.f;
    int i0 = lane * 24;
    #pragma unroll 4
    for (int j = 0; j < 24; j++) {
        int i = i0 + j;                   // i = h*64 + q, contiguous per lane
        int h = i >> 6, q = i & 63;
        size_t off = (((size_t)(b*NH + h)) * NTOK + q) * NTOK + NT + s;
        float e = __fadd_rn(cr[off], ct[off]);  // fp32 elementwise add
        acc = __fadd_rn(acc, e);                // sequential chain
    }
    #pragma unroll
    for (int o = 16; o > 0; o >>= 1)
        acc = __fadd_rn(acc, __shfl_down_sync(0xffffffffu, acc, o));
    if (lane == 0) g_score[b*NS + s] = __fmul_rn(acc, (1.0f / 768.0f));
}

// ---------------- stable descending argsort (bitonic 256, fp32 keys) ----------------
__global__ void sort_kernel(const int* __restrict__ gidx_s,
                            float* __restrict__ out_gs, float* __restrict__ out_rm) {
    __shared__ float sk[256];
    __shared__ int   si[256];
    int b = blockIdx.x, tid = threadIdx.x;
    sk[tid] = g_score[b*NS + tid];
    si[tid] = tid;
    __syncthreads();
    for (int k = 2; k <= 256; k <<= 1) {
        for (int j = k >> 1; j > 0; j >>= 1) {
            int ixj = tid ^ j;
            if (ixj > tid) {
                float ka = sk[tid], kb = sk[ixj];
                int ia = si[tid], ib = si[ixj];
                bool before = (ka > kb) || (ka == kb && ia < ib);
                bool up = ((tid & k) == 0);
                if (up ? !before : before) {
                    sk[tid] = kb; sk[ixj] = ka;
                    si[tid] = ib; si[ixj] = ia;
                }
            }
            __syncthreads();
        }
    }
    int idx = si[tid];
    float gv = (float)gidx_s[b*NS + idx];
    if (tid < NKEEP) {
        out_gs[b*NKEEP + tid] = gv;
        g_topk[b*NKEEP + tid] = idx;
    } else {
        out_rm[b*NREM + (tid - NKEEP)] = gv;
    }
}

// ---------------- copy global_index_t (int -> float) ----------------
__global__ void copy_gt_kernel(const int* __restrict__ gt, float* __restrict__ o) {
    int i = blockIdx.x * 256 + threadIdx.x;
    if (i < BATCH * NT) o[i] = (float)gt[i];
}

// ---------------- token gather (apply keep) ----------------
__global__ void gather_kernel(const float* __restrict__ xres, float* __restrict__ outx) {
    int bt = blockIdx.x;
    int b = bt / NOUT, t = bt % NOUT;
    int src = (t < NT) ? t : NT + g_topk[b*NKEEP + (t - NT)];
    const float* s = xres + ((size_t)(b*NTOK + src)) * DIM;
    float* d = outx + (size_t)bt * DIM;
    for (int c = threadIdx.x; c < DIM; c += 256) d[c] = s[c];
}

// ---------------- launcher ----------------
extern "C" void kernel_launch(void* const* d_in, const int* in_sizes, int n_in,
                              void* d_out, int out_size) {
    const float* x_rgb = (const float*)d_in[0];
    const float* x_tir = (const float*)d_in[1];
    const int*   gt    = (const int*)  d_in[2];
    const int*   gs    = (const int*)  d_in[3];
    const float* n1g = (const float*)d_in[4],  *n1b = (const float*)d_in[5];
    const float* qkvw= (const float*)d_in[6],  *qkvb= (const float*)d_in[7];
    const float* projw=(const float*)d_in[8],  *projb=(const float*)d_in[9];
    const float* n2g = (const float*)d_in[10], *n2b = (const float*)d_in[11];
    const float* fc1w= (const float*)d_in[12], *fc1b= (const float*)d_in[13];
    const float* fc2w= (const float*)d_in[14], *fc2b= (const float*)d_in[15];
    float* out = (float*)d_out;

    float *ln, *q, *k, *v, *av, *xr0, *xr1, *hbuf;
    cudaGetSymbolAddress((void**)&ln,   g_ln);
    cudaGetSymbolAddress((void**)&q,    g_q);
    cudaGetSymbolAddress((void**)&k,    g_k);
    cudaGetSymbolAddress((void**)&v,    g_v);
    cudaGetSymbolAddress((void**)&av,   g_av);
    cudaGetSymbolAddress((void**)&xr0,  g_xres0);
    cudaGetSymbolAddress((void**)&xr1,  g_xres1);
    cudaGetSymbolAddress((void**)&hbuf, g_h);

    float* corr[2]       = { out + OFF_CR, out + OFF_CT };
    const float* xin[2]  = { x_rgb, x_tir };
    float* xres[2]       = { xr0, xr1 };
    float* xout[2]       = { out + OFF_XRGB, out + OFF_XTIR };

    for (int m = 0; m < 2; m++) {
        ln_kernel<<<M1, 256>>>(xin[m], ln, n1g, n1b);
        sgemm_kernel<<<dim3(2304/128, M1/128), 256>>>(
            ln, qkvw, qkvb, M1, 2304, DIM, EPI_QKV, nullptr, nullptr, q, k, v);
        logits_kernel<<<dim3(NTOK/32, NTOK/32, BATCH*NH), 256>>>(q, k, corr[m]);
        softmax_kernel<<<(BATCH*NH*NTOK)/8, 256>>>(corr[m]);
        av_kernel<<<dim3(NTOK/32, BATCH*NH), 256>>>(corr[m], v, av);
        tf32gemm_kernel<<<dim3(DIM/128, M1/128), 256>>>(
            av, projw, projb, M1, DIM, DIM, TEPI_RES, xres[m], xin[m]);
    }

    score_kernel<<<(BATCH*NS*32)/256, 256>>>(corr[0], corr[1]);
    sort_kernel<<<BATCH, 256>>>(gs, out + OFF_GS, out + OFF_RM);
    copy_gt_kernel<<<(BATCH*NT + 255)/256, 256>>>(gt, out + OFF_GT);

    for (int m = 0; m < 2; m++)
        gather_kernel<<<BATCH*NOUT, 256>>>(xres[m], xout[m]);

    for (int m = 0; m < 2; m++) {
        ln_kernel<<<M2, 256>>>(xout[m], ln, n2g, n2b);
        tf32gemm_kernel<<<dim3(MLPH/128, M2/128), 256>>>(
            ln, fc1w, fc1b, M2, MLPH, DIM, TEPI_GELU, hbuf, nullptr);
        tf32gemm_kernel<<<dim3(DIM/128, M2/128), 256>>>(
            hbuf, fc2w, fc2b, M2, DIM, MLPH, TEPI_ADD, xout[m], nullptr);
    }
}

// round 13
// speedup vs baseline: 1.7856x; 1.0815x over previous
#include <cuda_runtime.h>
#include <math.h>
#include <stdint.h>

// ---------------- problem constants ----------------
#define BATCH 64
#define NTOK  320
#define NT    64
#define NS    256
#define DIM   768
#define NH    12
#define HD    64
#define MLPH  3072
#define NKEEP 180
#define NREM  76
#define NOUT  244
#define M1    (BATCH*NTOK)   // 20480
#define M2    (BATCH*NOUT)   // 15616

// output layout (flat float32)
#define OFF_XRGB 0LL
#define OFF_XTIR 11993088LL
#define OFF_GT   23986176LL
#define OFF_GS   23990272LL
#define OFF_RM   24001792LL
#define OFF_CR   24006656LL
#define OFF_CT   102649856LL

// ---------------- device scratch ----------------
__device__ float g_ln[(size_t)M1*DIM];
__device__ float g_q [(size_t)BATCH*NH*NTOK*HD];
__device__ float g_k [(size_t)BATCH*NH*NTOK*HD];
__device__ float g_v [(size_t)BATCH*NH*NTOK*HD];
__device__ float g_av[(size_t)M1*DIM];
__device__ float g_xres0[(size_t)M1*DIM];
__device__ float g_xres1[(size_t)M1*DIM];
__device__ float g_h [(size_t)M2*MLPH];
__device__ float g_score[BATCH*NS];
__device__ int   g_topk[BATCH*NKEEP];

// ---------------- reductions ----------------
__device__ __forceinline__ float block_sum(float v, float* red) {
    #pragma unroll
    for (int o = 16; o > 0; o >>= 1) v += __shfl_xor_sync(0xffffffffu, v, o);
    int tid = threadIdx.x;
    if ((tid & 31) == 0) red[tid >> 5] = v;
    __syncthreads();
    if (tid < 32) {
        float t = (tid < 8) ? red[tid] : 0.f;
        #pragma unroll
        for (int o = 4; o > 0; o >>= 1) t += __shfl_xor_sync(0xffffffffu, t, o);
        if (tid == 0) red[0] = t;
    }
    __syncthreads();
    float r = red[0];
    __syncthreads();
    return r;
}

// ---------------- LayerNorm (row = token of 768), block tree ----------------
__global__ void ln_kernel(const float* __restrict__ in, float* __restrict__ out,
                          const float* __restrict__ gam, const float* __restrict__ bet) {
    __shared__ float red[32];
    size_t row = blockIdx.x;
    const float* x = in + row * DIM;
    float* o = out + row * DIM;
    int tid = threadIdx.x;           // 256
    float lv[3];
    float s = 0.f;
    #pragma unroll
    for (int i = 0; i < 3; i++) { lv[i] = x[tid + i*256]; s += lv[i]; }
    float mean = block_sum(s, red) * (1.0f / DIM);
    float vs = 0.f;
    #pragma unroll
    for (int i = 0; i < 3; i++) { float d = lv[i] - mean; vs += d * d; }
    float var = block_sum(vs, red) * (1.0f / DIM);
    float rstd = rsqrtf(var + 1e-5f);
    #pragma unroll
    for (int i = 0; i < 3; i++) {
        int c = tid + i*256;
        o[c] = (lv[i] - mean) * rstd * gam[c] + bet[c];
    }
}

// ---------------- exact fp32 SGEMM, double-buffered K16 (QKV only) ---------
// Per-output FMA chain remains single-accumulator, strictly k-ascending ->
// bit-identical to the single-buffered version (ranking path safe).
__global__ void __launch_bounds__(256) sgemm_kernel(
    const float* __restrict__ A, const float* __restrict__ W,
    const float* __restrict__ bias, int M, int N, int K,
    float* __restrict__ qp, float* __restrict__ kp, float* __restrict__ vp) {

    __shared__ float As[2][16][128];
    __shared__ float Bs[2][16][128];
    int tid = threadIdx.x;
    int bm = blockIdx.y * 128, bn = blockIdx.x * 128;
    int ty = tid >> 4, tx = tid & 15;

    float acc[8][8];
    #pragma unroll
    for (int i = 0; i < 8; i++)
        #pragma unroll
        for (int j = 0; j < 8; j++) acc[i][j] = 0.f;

    int arow = tid >> 1, acol = (tid & 1) * 8;
    int brow = tid >> 4, bcol = (tid & 15) * 8;
    const float* Aptr = A + (size_t)(bm + arow) * K + acol;
    const float* Wptr = W + (size_t)brow * N + bn + bcol;

    // preload tile 0
    float4 a0 = *(const float4*)(Aptr);
    float4 a1 = *(const float4*)(Aptr + 4);
    float4 b0 = *(const float4*)(Wptr);
    float4 b1 = *(const float4*)(Wptr + 4);
    As[0][acol+0][arow] = a0.x; As[0][acol+1][arow] = a0.y;
    As[0][acol+2][arow] = a0.z; As[0][acol+3][arow] = a0.w;
    As[0][acol+4][arow] = a1.x; As[0][acol+5][arow] = a1.y;
    As[0][acol+6][arow] = a1.z; As[0][acol+7][arow] = a1.w;
    *(float4*)&Bs[0][brow][bcol]     = b0;
    *(float4*)&Bs[0][brow][bcol + 4] = b1;
    __syncthreads();

    int buf = 0;
    for (int k0 = 16; k0 <= K; k0 += 16) {
        if (k0 < K) {
            a0 = *(const float4*)(Aptr + k0);
            a1 = *(const float4*)(Aptr + k0 + 4);
            b0 = *(const float4*)(Wptr + (size_t)k0 * N);
            b1 = *(const float4*)(Wptr + (size_t)k0 * N + 4);
        }
        #pragma unroll
        for (int kk = 0; kk < 16; kk++) {
            float ra[8], rb[8];
            #pragma unroll
            for (int i = 0; i < 8; i++) ra[i] = As[buf][kk][ty*8 + i];
            #pragma unroll
            for (int j = 0; j < 8; j++) rb[j] = Bs[buf][kk][tx*8 + j];
            #pragma unroll
            for (int i = 0; i < 8; i++)
                #pragma unroll
                for (int j = 0; j < 8; j++)
                    acc[i][j] = fmaf(ra[i], rb[j], acc[i][j]);
        }
        if (k0 < K) {
            int nb = buf ^ 1;
            As[nb][acol+0][arow] = a0.x; As[nb][acol+1][arow] = a0.y;
            As[nb][acol+2][arow] = a0.z; As[nb][acol+3][arow] = a0.w;
            As[nb][acol+4][arow] = a1.x; As[nb][acol+5][arow] = a1.y;
            As[nb][acol+6][arow] = a1.z; As[nb][acol+7][arow] = a1.w;
            *(float4*)&Bs[nb][brow][bcol]     = b0;
            *(float4*)&Bs[nb][brow][bcol + 4] = b1;
            __syncthreads();
            buf = nb;
        }
    }

    #pragma unroll
    for (int i = 0; i < 8; i++) {
        int r = bm + ty*8 + i;
        #pragma unroll
        for (int j = 0; j < 8; j++) {
            int c = bn + tx*8 + j;
            float val = acc[i][j] + bias[c];
            int which = c / 768;
            int h = (c % 768) >> 6;
            int d = c & 63;
            int b = r / NTOK, n = r % NTOK;
            size_t dst = (((size_t)(b*NH + h)) * NTOK + n) * HD + d;
            float* base = (which == 0) ? qp : (which == 1) ? kp : vp;
            base[dst] = val;
        }
    }
}

// ---------------- TF32 tensor-core GEMM, double-buffered (proj/fc1/fc2) -----
#define TEPI_RES  1
#define TEPI_GELU 2
#define TEPI_ADD  3
#define SPAD 8

__device__ __forceinline__ uint32_t f2tf32(float f) {
    uint32_t r;
    asm("cvt.rna.tf32.f32 %0, %1;" : "=r"(r) : "f"(f));
    return r;
}

__device__ __forceinline__ void mma_tf32(float* c, const uint32_t* a, const uint32_t* b) {
    asm volatile(
        "mma.sync.aligned.m16n8k8.row.col.f32.tf32.tf32.f32 "
        "{%0,%1,%2,%3}, {%4,%5,%6,%7}, {%8,%9}, {%0,%1,%2,%3};"
        : "+f"(c[0]), "+f"(c[1]), "+f"(c[2]), "+f"(c[3])
        : "r"(a[0]), "r"(a[1]), "r"(a[2]), "r"(a[3]), "r"(b[0]), "r"(b[1]));
}

__global__ void __launch_bounds__(256) tf32gemm_kernel(
    const float* __restrict__ A, const float* __restrict__ W,
    const float* __restrict__ bias, int M, int N, int K, int mode,
    float* __restrict__ out, const float* __restrict__ aux) {

    __shared__ uint32_t As[2][16][128 + SPAD];
    __shared__ uint32_t Bs[2][16][128 + SPAD];

    int tid = threadIdx.x;
    int bm = blockIdx.y * 128, bn = blockIdx.x * 128;
    int warp = tid >> 5, lane = tid & 31;
    int g = lane >> 2, ctg = lane & 3;
    int wr = (warp >> 2) * 64;   // 0 / 64
    int wc = (warp & 3) * 32;    // 0,32,64,96

    float acc[4][4][4];
    #pragma unroll
    for (int mt = 0; mt < 4; mt++)
        #pragma unroll
        for (int nt = 0; nt < 4; nt++)
            #pragma unroll
            for (int r = 0; r < 4; r++) acc[mt][nt][r] = 0.f;

    int arow = tid >> 1, acol0 = (tid & 1) * 8;
    int brow = tid >> 4, bcol0 = (tid & 15) * 8;
    const float* Ap = A + (size_t)(bm + arow) * K;
    const float* Wp = W + bn;

    // preload tile 0
    float4 av0 = *(const float4*)(Ap + acol0);
    float4 av1 = *(const float4*)(Ap + acol0 + 4);
    float4 bv0 = *(const float4*)(Wp + (size_t)brow * N + bcol0);
    float4 bv1 = *(const float4*)(Wp + (size_t)brow * N + bcol0 + 4);

    {
        As[0][acol0+0][arow] = f2tf32(av0.x); As[0][acol0+1][arow] = f2tf32(av0.y);
        As[0][acol0+2][arow] = f2tf32(av0.z); As[0][acol0+3][arow] = f2tf32(av0.w);
        As[0][acol0+4][arow] = f2tf32(av1.x); As[0][acol0+5][arow] = f2tf32(av1.y);
        As[0][acol0+6][arow] = f2tf32(av1.z); As[0][acol0+7][arow] = f2tf32(av1.w);
        uint4 bu0, bu1;
        bu0.x = f2tf32(bv0.x); bu0.y = f2tf32(bv0.y);
        bu0.z = f2tf32(bv0.z); bu0.w = f2tf32(bv0.w);
        bu1.x = f2tf32(bv1.x); bu1.y = f2tf32(bv1.y);
        bu1.z = f2tf32(bv1.z); bu1.w = f2tf32(bv1.w);
        *(uint4*)&Bs[0][brow][bcol0]     = bu0;
        *(uint4*)&Bs[0][brow][bcol0 + 4] = bu1;
    }
    __syncthreads();

    int buf = 0;
    for (int k0 = 16; k0 <= K; k0 += 16) {
        if (k0 < K) {
            av0 = *(const float4*)(Ap + k0 + acol0);
            av1 = *(const float4*)(Ap + k0 + acol0 + 4);
            bv0 = *(const float4*)(Wp + (size_t)(k0 + brow) * N + bcol0);
            bv1 = *(const float4*)(Wp + (size_t)(k0 + brow) * N + bcol0 + 4);
        }
        #pragma unroll
        for (int ks = 0; ks < 16; ks += 8) {
            uint32_t af[4][4];
            #pragma unroll
            for (int mt = 0; mt < 4; mt++) {
                int m0 = wr + mt*16 + g;
                af[mt][0] = As[buf][ks+ctg  ][m0];
                af[mt][1] = As[buf][ks+ctg  ][m0+8];
                af[mt][2] = As[buf][ks+ctg+4][m0];
                af[mt][3] = As[buf][ks+ctg+4][m0+8];
            }
            uint32_t bf[4][2];
            #pragma unroll
            for (int nt = 0; nt < 4; nt++) {
                int n0 = wc + nt*8 + g;
                bf[nt][0] = Bs[buf][ks+ctg  ][n0];
                bf[nt][1] = Bs[buf][ks+ctg+4][n0];
            }
            #pragma unroll
            for (int mt = 0; mt < 4; mt++)
                #pragma unroll
                for (int nt = 0; nt < 4; nt++)
                    mma_tf32(acc[mt][nt], af[mt], bf[nt]);
        }
        if (k0 < K) {
            int nb = buf ^ 1;
            As[nb][acol0+0][arow] = f2tf32(av0.x); As[nb][acol0+1][arow] = f2tf32(av0.y);
            As[nb][acol0+2][arow] = f2tf32(av0.z); As[nb][acol0+3][arow] = f2tf32(av0.w);
            As[nb][acol0+4][arow] = f2tf32(av1.x); As[nb][acol0+5][arow] = f2tf32(av1.y);
            As[nb][acol0+6][arow] = f2tf32(av1.z); As[nb][acol0+7][arow] = f2tf32(av1.w);
            uint4 bu0, bu1;
            bu0.x = f2tf32(bv0.x); bu0.y = f2tf32(bv0.y);
            bu0.z = f2tf32(bv0.z); bu0.w = f2tf32(bv0.w);
            bu1.x = f2tf32(bv1.x); bu1.y = f2tf32(bv1.y);
            bu1.z = f2tf32(bv1.z); bu1.w = f2tf32(bv1.w);
            *(uint4*)&Bs[nb][brow][bcol0]     = bu0;
            *(uint4*)&Bs[nb][brow][bcol0 + 4] = bu1;
            __syncthreads();
            buf = nb;
        }
    }

    #pragma unroll
    for (int mt = 0; mt < 4; mt++) {
        #pragma unroll
        for (int nt = 0; nt < 4; nt++) {
            int r0 = bm + wr + mt*16 + g;
            int c0 = bn + wc + nt*8 + ctg*2;
            #pragma unroll
            for (int rr = 0; rr < 2; rr++) {
                int r = r0 + rr*8;
                #pragma unroll
                for (int cc = 0; cc < 2; cc++) {
                    int c = c0 + cc;
                    float val = acc[mt][nt][rr*2 + cc] + bias[c];
                    size_t idx = (size_t)r * N + c;
                    if (mode == TEPI_RES)       out[idx] = val + aux[idx];
                    else if (mode == TEPI_GELU) out[idx] = val * normcdff(val);
                    else                        out[idx] += val;   // TEPI_ADD
                }
            }
        }
    }
}

// ---------------- attention: logits tile 32x32 (K=64) ----------------
__global__ void __launch_bounds__(256) logits_kernel(
    const float* __restrict__ q, const float* __restrict__ k, float* __restrict__ corr) {
    __shared__ float qs[32][65];
    __shared__ float ks[32][65];
    int tid = threadIdx.x;
    int bh = blockIdx.z;
    int m0 = blockIdx.y * 32, n0 = blockIdx.x * 32;
    const float* qb = q + ((size_t)bh * NTOK + m0) * HD;
    const float* kb = k + ((size_t)bh * NTOK + n0) * HD;
    for (int i = tid; i < 32*64; i += 256) {
        int r = i >> 6, c = i & 63;
        qs[r][c] = qb[(size_t)r * HD + c];
        ks[r][c] = kb[(size_t)r * HD + c];
    }
    __syncthreads();
    int ty = tid >> 5, tx = tid & 31;
    float acc0 = 0.f, acc1 = 0.f, acc2 = 0.f, acc3 = 0.f;
    #pragma unroll
    for (int d = 0; d < 64; d++) {
        float kv = ks[tx][d];
        acc0 = fmaf(qs[ty     ][d], kv, acc0);
        acc1 = fmaf(qs[ty + 8 ][d], kv, acc1);
        acc2 = fmaf(qs[ty + 16][d], kv, acc2);
        acc3 = fmaf(qs[ty + 24][d], kv, acc3);
    }
    float* cb = corr + ((size_t)bh * NTOK + m0) * NTOK + n0;
    cb[(size_t)(ty     ) * NTOK + tx] = acc0 * 0.125f;
    cb[(size_t)(ty + 8 ) * NTOK + tx] = acc1 * 0.125f;
    cb[(size_t)(ty + 16) * NTOK + tx] = acc2 * 0.125f;
    cb[(size_t)(ty + 24) * NTOK + tx] = acc3 * 0.125f;
}

// ---------------- softmax: warp per row, vec2 lanes ----------------
__global__ void __launch_bounds__(256) softmax_kernel(float* __restrict__ p) {
    int gwarp = (blockIdx.x * blockDim.x + threadIdx.x) >> 5;
    int lane = threadIdx.x & 31;
    float* x = p + (size_t)gwarp * NTOK;

    float v[10];
    #pragma unroll
    for (int i = 0; i < 5; i++) {
        v[2*i]   = x[64*i + 2*lane];
        v[2*i+1] = x[64*i + 2*lane + 1];
    }
    float m = v[0];
    #pragma unroll
    for (int j = 1; j < 10; j++) m = fmaxf(m, v[j]);
    #pragma unroll
    for (int o = 16; o > 0; o >>= 1)
        m = fmaxf(m, __shfl_down_sync(0xffffffffu, m, o));
    m = __shfl_sync(0xffffffffu, m, 0);

    float e[10];
    float a0 = 0.f, a1 = 0.f;
    #pragma unroll
    for (int i = 0; i < 5; i++) {
        e[2*i]   = expf(__fsub_rn(v[2*i],   m));
        e[2*i+1] = expf(__fsub_rn(v[2*i+1], m));
        a0 = __fadd_rn(a0, e[2*i]);
        a1 = __fadd_rn(a1, e[2*i+1]);
    }
    float S = __fadd_rn(a0, a1);
    #pragma unroll
    for (int o = 16; o > 0; o >>= 1)
        S = __fadd_rn(S, __shfl_down_sync(0xffffffffu, S, o));
    S = __shfl_sync(0xffffffffu, S, 0);

    #pragma unroll
    for (int i = 0; i < 5; i++) {
        x[64*i + 2*lane]     = __fdiv_rn(e[2*i],   S);
        x[64*i + 2*lane + 1] = __fdiv_rn(e[2*i+1], S);
    }
}

// ---------------- attention: O = P @ V (tile 32 rows x 64 cols) ----------------
__global__ void __launch_bounds__(256) av_kernel(
    const float* __restrict__ corr, const float* __restrict__ v, float* __restrict__ av) {
    __shared__ float Ps[32][33];
    __shared__ float Vs[32][65];
    int tid = threadIdx.x;
    int bh = blockIdx.y;
    int m0 = blockIdx.x * 32;
    int b = bh / NH, h = bh % NH;
    int ty = tid >> 6, tx = tid & 63;   // ty in [0,4)
    float acc[8];
    #pragma unroll
    for (int i = 0; i < 8; i++) acc[i] = 0.f;

    for (int k0 = 0; k0 < NTOK; k0 += 32) {
        for (int i = tid; i < 32*32; i += 256) {
            int r = i >> 5, c = i & 31;
            Ps[r][c] = corr[((size_t)bh * NTOK + m0 + r) * NTOK + k0 + c];
        }
        for (int i = tid; i < 32*64; i += 256) {
            int r = i >> 6, c = i & 63;
            Vs[r][c] = v[((size_t)bh * NTOK + k0 + r) * HD + c];
        }
        __syncthreads();
        #pragma unroll
        for (int kk = 0; kk < 32; kk++) {
            float vv = Vs[kk][tx];
            #pragma unroll
            for (int r8 = 0; r8 < 8; r8++)
                acc[r8] = fmaf(Ps[ty + 4*r8][kk], vv, acc[r8]);
        }
        __syncthreads();
    }
    #pragma unroll
    for (int r8 = 0; r8 < 8; r8++) {
        int n = m0 + ty + 4*r8;
        av[(((size_t)(b*NTOK + n)) * NH + h) * HD + tx] = acc[r8];
    }
}

// ---------------- saliency score: contig-24 chain + tree, recip-mul mean ----
__global__ void score_kernel(const float* __restrict__ cr, const float* __restrict__ ct) {
    int gwarp = (blockIdx.x * blockDim.x + threadIdx.x) >> 5;  // 0 .. BATCH*NS-1
    int lane = threadIdx.x & 31;
    int b = gwarp >> 8;        // / NS
    int s = gwarp & 255;       // % NS
    float acc = 0.f;
    int i0 = lane * 24;
    #pragma unroll 4
    for (int j = 0; j < 24; j++) {
        int i = i0 + j;                   // i = h*64 + q, contiguous per lane
        int h = i >> 6, q = i & 63;
        size_t off = (((size_t)(b*NH + h)) * NTOK + q) * NTOK + NT + s;
        float e = __fadd_rn(cr[off], ct[off]);  // fp32 elementwise add
        acc = __fadd_rn(acc, e);                // sequential chain
    }
    #pragma unroll
    for (int o = 16; o > 0; o >>= 1)
        acc = __fadd_rn(acc, __shfl_down_sync(0xffffffffu, acc, o));
    if (lane == 0) g_score[b*NS + s] = __fmul_rn(acc, (1.0f / 768.0f));
}

// ---------------- stable descending argsort (bitonic 256, fp32 keys) ----------------
__global__ void sort_kernel(const int* __restrict__ gidx_s,
                            float* __restrict__ out_gs, float* __restrict__ out_rm) {
    __shared__ float sk[256];
    __shared__ int   si[256];
    int b = blockIdx.x, tid = threadIdx.x;
    sk[tid] = g_score[b*NS + tid];
    si[tid] = tid;
    __syncthreads();
    for (int k = 2; k <= 256; k <<= 1) {
        for (int j = k >> 1; j > 0; j >>= 1) {
            int ixj = tid ^ j;
            if (ixj > tid) {
                float ka = sk[tid], kb = sk[ixj];
                int ia = si[tid], ib = si[ixj];
                bool before = (ka > kb) || (ka == kb && ia < ib);
                bool up = ((tid & k) == 0);
                if (up ? !before : before) {
                    sk[tid] = kb; sk[ixj] = ka;
                    si[tid] = ib; si[ixj] = ia;
                }
            }
            __syncthreads();
        }
    }
    int idx = si[tid];
    float gv = (float)gidx_s[b*NS + idx];
    if (tid < NKEEP) {
        out_gs[b*NKEEP + tid] = gv;
        g_topk[b*NKEEP + tid] = idx;
    } else {
        out_rm[b*NREM + (tid - NKEEP)] = gv;
    }
}

// ---------------- copy global_index_t (int -> float) ----------------
__global__ void copy_gt_kernel(const int* __restrict__ gt, float* __restrict__ o) {
    int i = blockIdx.x * 256 + threadIdx.x;
    if (i < BATCH * NT) o[i] = (float)gt[i];
}

// ---------------- token gather (apply keep) ----------------
__global__ void gather_kernel(const float* __restrict__ xres, float* __restrict__ outx) {
    int bt = blockIdx.x;
    int b = bt / NOUT, t = bt % NOUT;
    int src = (t < NT) ? t : NT + g_topk[b*NKEEP + (t - NT)];
    const float* s = xres + ((size_t)(b*NTOK + src)) * DIM;
    float* d = outx + (size_t)bt * DIM;
    for (int c = threadIdx.x; c < DIM; c += 256) d[c] = s[c];
}

// ---------------- launcher ----------------
extern "C" void kernel_launch(void* const* d_in, const int* in_sizes, int n_in,
                              void* d_out, int out_size) {
    const float* x_rgb = (const float*)d_in[0];
    const float* x_tir = (const float*)d_in[1];
    const int*   gt    = (const int*)  d_in[2];
    const int*   gs    = (const int*)  d_in[3];
    const float* n1g = (const float*)d_in[4],  *n1b = (const float*)d_in[5];
    const float* qkvw= (const float*)d_in[6],  *qkvb= (const float*)d_in[7];
    const float* projw=(const float*)d_in[8],  *projb=(const float*)d_in[9];
    const float* n2g = (const float*)d_in[10], *n2b = (const float*)d_in[11];
    const float* fc1w= (const float*)d_in[12], *fc1b= (const float*)d_in[13];
    const float* fc2w= (const float*)d_in[14], *fc2b= (const float*)d_in[15];
    float* out = (float*)d_out;

    float *ln, *q, *k, *v, *av, *xr0, *xr1, *hbuf;
    cudaGetSymbolAddress((void**)&ln,   g_ln);
    cudaGetSymbolAddress((void**)&q,    g_q);
    cudaGetSymbolAddress((void**)&k,    g_k);
    cudaGetSymbolAddress((void**)&v,    g_v);
    cudaGetSymbolAddress((void**)&av,   g_av);
    cudaGetSymbolAddress((void**)&xr0,  g_xres0);
    cudaGetSymbolAddress((void**)&xr1,  g_xres1);
    cudaGetSymbolAddress((void**)&hbuf, g_h);

    float* corr[2]       = { out + OFF_CR, out + OFF_CT };
    const float* xin[2]  = { x_rgb, x_tir };
    float* xres[2]       = { xr0, xr1 };
    float* xout[2]       = { out + OFF_XRGB, out + OFF_XTIR };

    for (int m = 0; m < 2; m++) {
        ln_kernel<<<M1, 256>>>(xin[m], ln, n1g, n1b);
        sgemm_kernel<<<dim3(2304/128, M1/128), 256>>>(
            ln, qkvw, qkvb, M1, 2304, DIM, q, k, v);
        logits_kernel<<<dim3(NTOK/32, NTOK/32, BATCH*NH), 256>>>(q, k, corr[m]);
        softmax_kernel<<<(BATCH*NH*NTOK)/8, 256>>>(corr[m]);
        av_kernel<<<dim3(NTOK/32, BATCH*NH), 256>>>(corr[m], v, av);
        tf32gemm_kernel<<<dim3(DIM/128, M1/128), 256>>>(
            av, projw, projb, M1, DIM, DIM, TEPI_RES, xres[m], xin[m]);
    }

    score_kernel<<<(BATCH*NS*32)/256, 256>>>(corr[0], corr[1]);
    sort_kernel<<<BATCH, 256>>>(gs, out + OFF_GS, out + OFF_RM);
    copy_gt_kernel<<<(BATCH*NT + 255)/256, 256>>>(gt, out + OFF_GT);

    for (int m = 0; m < 2; m++)
        gather_kernel<<<BATCH*NOUT, 256>>>(xres[m], xout[m]);

    for (int m = 0; m < 2; m++) {
        ln_kernel<<<M2, 256>>>(xout[m], ln, n2g, n2b);
        tf32gemm_kernel<<<dim3(MLPH/128, M2/128), 256>>>(
            ln, fc1w, fc1b, M2, MLPH, DIM, TEPI_GELU, hbuf, nullptr);
        tf32gemm_kernel<<<dim3(DIM/128, M2/128), 256>>>(
            hbuf, fc2w, fc2b, M2, DIM, MLPH, TEPI_ADD, xout[m], nullptr);
    }
}

// round 14
// speedup vs baseline: 2.1689x; 1.2147x over previous
#include <cuda_runtime.h>
#include <math.h>
#include <stdint.h>

// ---------------- problem constants ----------------
#define BATCH 64
#define NTOK  320
#define NT    64
#define NS    256
#define DIM   768
#define NH    12
#define HD    64
#define MLPH  3072
#define NKEEP 180
#define NREM  76
#define NOUT  244
#define M1    (BATCH*NTOK)   // 20480
#define M2    (BATCH*NOUT)   // 15616

// output layout (flat float32)
#define OFF_XRGB 0LL
#define OFF_XTIR 11993088LL
#define OFF_GT   23986176LL
#define OFF_GS   23990272LL
#define OFF_RM   24001792LL
#define OFF_CR   24006656LL
#define OFF_CT   102649856LL

// ---------------- device scratch ----------------
__device__ float g_ln[(size_t)M1*DIM];
__device__ float g_q [(size_t)BATCH*NH*NTOK*HD];
__device__ float g_k [(size_t)BATCH*NH*NTOK*HD];
__device__ float g_v [(size_t)BATCH*NH*NTOK*HD];
__device__ float g_av[(size_t)M1*DIM];
__device__ float g_xres0[(size_t)M1*DIM];
__device__ float g_xres1[(size_t)M1*DIM];
__device__ float g_h [(size_t)M2*MLPH];
__device__ float g_score[BATCH*NS];
__device__ int   g_topk[BATCH*NKEEP];

// ---------------- reductions ----------------
__device__ __forceinline__ float block_sum(float v, float* red) {
    #pragma unroll
    for (int o = 16; o > 0; o >>= 1) v += __shfl_xor_sync(0xffffffffu, v, o);
    int tid = threadIdx.x;
    if ((tid & 31) == 0) red[tid >> 5] = v;
    __syncthreads();
    if (tid < 32) {
        float t = (tid < 8) ? red[tid] : 0.f;
        #pragma unroll
        for (int o = 4; o > 0; o >>= 1) t += __shfl_xor_sync(0xffffffffu, t, o);
        if (tid == 0) red[0] = t;
    }
    __syncthreads();
    float r = red[0];
    __syncthreads();
    return r;
}

// ---------------- LayerNorm (row = token of 768), block tree ----------------
__global__ void ln_kernel(const float* __restrict__ in, float* __restrict__ out,
                          const float* __restrict__ gam, const float* __restrict__ bet) {
    __shared__ float red[32];
    size_t row = blockIdx.x;
    const float* x = in + row * DIM;
    float* o = out + row * DIM;
    int tid = threadIdx.x;           // 256
    float lv[3];
    float s = 0.f;
    #pragma unroll
    for (int i = 0; i < 3; i++) { lv[i] = x[tid + i*256]; s += lv[i]; }
    float mean = block_sum(s, red) * (1.0f / DIM);
    float vs = 0.f;
    #pragma unroll
    for (int i = 0; i < 3; i++) { float d = lv[i] - mean; vs += d * d; }
    float var = block_sum(vs, red) * (1.0f / DIM);
    float rstd = rsqrtf(var + 1e-5f);
    #pragma unroll
    for (int i = 0; i < 3; i++) {
        int c = tid + i*256;
        o[c] = (lv[i] - mean) * rstd * gam[c] + bet[c];
    }
}

// ---------------- exact fp32 SGEMM, double-buffered K16 (Q,K only) ---------
// N = 1536 (q|k columns of qkv weight), weight row stride ldw = 2304.
// Per-output FMA chain single-accumulator, strictly k-ascending (bit-exact).
__global__ void __launch_bounds__(256) sgemm_kernel(
    const float* __restrict__ A, const float* __restrict__ W,
    const float* __restrict__ bias, int K, int ldw,
    float* __restrict__ qp, float* __restrict__ kp) {

    __shared__ float As[2][16][128];
    __shared__ float Bs[2][16][128];
    int tid = threadIdx.x;
    int bm = blockIdx.y * 128, bn = blockIdx.x * 128;
    int ty = tid >> 4, tx = tid & 15;

    float acc[8][8];
    #pragma unroll
    for (int i = 0; i < 8; i++)
        #pragma unroll
        for (int j = 0; j < 8; j++) acc[i][j] = 0.f;

    int arow = tid >> 1, acol = (tid & 1) * 8;
    int brow = tid >> 4, bcol = (tid & 15) * 8;
    const float* Aptr = A + (size_t)(bm + arow) * K + acol;
    const float* Wptr = W + (size_t)brow * ldw + bn + bcol;

    float4 a0 = *(const float4*)(Aptr);
    float4 a1 = *(const float4*)(Aptr + 4);
    float4 b0 = *(const float4*)(Wptr);
    float4 b1 = *(const float4*)(Wptr + 4);
    As[0][acol+0][arow] = a0.x; As[0][acol+1][arow] = a0.y;
    As[0][acol+2][arow] = a0.z; As[0][acol+3][arow] = a0.w;
    As[0][acol+4][arow] = a1.x; As[0][acol+5][arow] = a1.y;
    As[0][acol+6][arow] = a1.z; As[0][acol+7][arow] = a1.w;
    *(float4*)&Bs[0][brow][bcol]     = b0;
    *(float4*)&Bs[0][brow][bcol + 4] = b1;
    __syncthreads();

    int buf = 0;
    for (int k0 = 16; k0 <= K; k0 += 16) {
        if (k0 < K) {
            a0 = *(const float4*)(Aptr + k0);
            a1 = *(const float4*)(Aptr + k0 + 4);
            b0 = *(const float4*)(Wptr + (size_t)k0 * ldw);
            b1 = *(const float4*)(Wptr + (size_t)k0 * ldw + 4);
        }
        #pragma unroll
        for (int kk = 0; kk < 16; kk++) {
            float ra[8], rb[8];
            #pragma unroll
            for (int i = 0; i < 8; i++) ra[i] = As[buf][kk][ty*8 + i];
            #pragma unroll
            for (int j = 0; j < 8; j++) rb[j] = Bs[buf][kk][tx*8 + j];
            #pragma unroll
            for (int i = 0; i < 8; i++)
                #pragma unroll
                for (int j = 0; j < 8; j++)
                    acc[i][j] = fmaf(ra[i], rb[j], acc[i][j]);
        }
        if (k0 < K) {
            int nb = buf ^ 1;
            As[nb][acol+0][arow] = a0.x; As[nb][acol+1][arow] = a0.y;
            As[nb][acol+2][arow] = a0.z; As[nb][acol+3][arow] = a0.w;
            As[nb][acol+4][arow] = a1.x; As[nb][acol+5][arow] = a1.y;
            As[nb][acol+6][arow] = a1.z; As[nb][acol+7][arow] = a1.w;
            *(float4*)&Bs[nb][brow][bcol]     = b0;
            *(float4*)&Bs[nb][brow][bcol + 4] = b1;
            __syncthreads();
            buf = nb;
        }
    }

    #pragma unroll
    for (int i = 0; i < 8; i++) {
        int r = bm + ty*8 + i;
        #pragma unroll
        for (int j = 0; j < 8; j++) {
            int c = bn + tx*8 + j;          // c in [0,1536)
            float val = acc[i][j] + bias[c];
            int which = c >> 9 >> 1;        // placeholder, computed below
            which = c / 768;                // 0 = q, 1 = k
            int h = (c % 768) >> 6;
            int d = c & 63;
            int b = r / NTOK, n = r % NTOK;
            size_t dst = (((size_t)(b*NH + h)) * NTOK + n) * HD + d;
            float* base = (which == 0) ? qp : kp;
            base[dst] = val;
        }
    }
}

// ---------------- TF32 tensor-core GEMM (proj / fc1 / fc2 / V) --------------
#define TEPI_RES  1
#define TEPI_GELU 2
#define TEPI_ADD  3
#define TEPI_V    4
#define SPAD 8

__device__ __forceinline__ uint32_t f2tf32(float f) {
    uint32_t r;
    asm("cvt.rna.tf32.f32 %0, %1;" : "=r"(r) : "f"(f));
    return r;
}

__device__ __forceinline__ void mma_tf32(float* c, const uint32_t* a, const uint32_t* b) {
    asm volatile(
        "mma.sync.aligned.m16n8k8.row.col.f32.tf32.tf32.f32 "
        "{%0,%1,%2,%3}, {%4,%5,%6,%7}, {%8,%9}, {%0,%1,%2,%3};"
        : "+f"(c[0]), "+f"(c[1]), "+f"(c[2]), "+f"(c[3])
        : "r"(a[0]), "r"(a[1]), "r"(a[2]), "r"(a[3]), "r"(b[0]), "r"(b[1]));
}

__global__ void __launch_bounds__(256) tf32gemm_kernel(
    const float* __restrict__ A, const float* __restrict__ W,
    const float* __restrict__ bias, int M, int N, int K, int ldw, int mode,
    float* __restrict__ out, const float* __restrict__ aux) {

    __shared__ uint32_t As[2][16][128 + SPAD];
    __shared__ uint32_t Bs[2][16][128 + SPAD];

    int tid = threadIdx.x;
    int bm = blockIdx.y * 128, bn = blockIdx.x * 128;
    int warp = tid >> 5, lane = tid & 31;
    int g = lane >> 2, ctg = lane & 3;
    int wr = (warp >> 2) * 64;
    int wc = (warp & 3) * 32;

    float acc[4][4][4];
    #pragma unroll
    for (int mt = 0; mt < 4; mt++)
        #pragma unroll
        for (int nt = 0; nt < 4; nt++)
            #pragma unroll
            for (int r = 0; r < 4; r++) acc[mt][nt][r] = 0.f;

    int arow = tid >> 1, acol0 = (tid & 1) * 8;
    int brow = tid >> 4, bcol0 = (tid & 15) * 8;
    const float* Ap = A + (size_t)(bm + arow) * K;
    const float* Wp = W + bn;

    float4 av0 = *(const float4*)(Ap + acol0);
    float4 av1 = *(const float4*)(Ap + acol0 + 4);
    float4 bv0 = *(const float4*)(Wp + (size_t)brow * ldw + bcol0);
    float4 bv1 = *(const float4*)(Wp + (size_t)brow * ldw + bcol0 + 4);

    {
        As[0][acol0+0][arow] = f2tf32(av0.x); As[0][acol0+1][arow] = f2tf32(av0.y);
        As[0][acol0+2][arow] = f2tf32(av0.z); As[0][acol0+3][arow] = f2tf32(av0.w);
        As[0][acol0+4][arow] = f2tf32(av1.x); As[0][acol0+5][arow] = f2tf32(av1.y);
        As[0][acol0+6][arow] = f2tf32(av1.z); As[0][acol0+7][arow] = f2tf32(av1.w);
        uint4 bu0, bu1;
        bu0.x = f2tf32(bv0.x); bu0.y = f2tf32(bv0.y);
        bu0.z = f2tf32(bv0.z); bu0.w = f2tf32(bv0.w);
        bu1.x = f2tf32(bv1.x); bu1.y = f2tf32(bv1.y);
        bu1.z = f2tf32(bv1.z); bu1.w = f2tf32(bv1.w);
        *(uint4*)&Bs[0][brow][bcol0]     = bu0;
        *(uint4*)&Bs[0][brow][bcol0 + 4] = bu1;
    }
    __syncthreads();

    int buf = 0;
    for (int k0 = 16; k0 <= K; k0 += 16) {
        if (k0 < K) {
            av0 = *(const float4*)(Ap + k0 + acol0);
            av1 = *(const float4*)(Ap + k0 + acol0 + 4);
            bv0 = *(const float4*)(Wp + (size_t)(k0 + brow) * ldw + bcol0);
            bv1 = *(const float4*)(Wp + (size_t)(k0 + brow) * ldw + bcol0 + 4);
        }
        #pragma unroll
        for (int ks = 0; ks < 16; ks += 8) {
            uint32_t af[4][4];
            #pragma unroll
            for (int mt = 0; mt < 4; mt++) {
                int m0 = wr + mt*16 + g;
                af[mt][0] = As[buf][ks+ctg  ][m0];
                af[mt][1] = As[buf][ks+ctg  ][m0+8];
                af[mt][2] = As[buf][ks+ctg+4][m0];
                af[mt][3] = As[buf][ks+ctg+4][m0+8];
            }
            uint32_t bf[4][2];
            #pragma unroll
            for (int nt = 0; nt < 4; nt++) {
                int n0 = wc + nt*8 + g;
                bf[nt][0] = Bs[buf][ks+ctg  ][n0];
                bf[nt][1] = Bs[buf][ks+ctg+4][n0];
            }
            #pragma unroll
            for (int mt = 0; mt < 4; mt++)
                #pragma unroll
                for (int nt = 0; nt < 4; nt++)
                    mma_tf32(acc[mt][nt], af[mt], bf[nt]);
        }
        if (k0 < K) {
            int nb = buf ^ 1;
            As[nb][acol0+0][arow] = f2tf32(av0.x); As[nb][acol0+1][arow] = f2tf32(av0.y);
            As[nb][acol0+2][arow] = f2tf32(av0.z); As[nb][acol0+3][arow] = f2tf32(av0.w);
            As[nb][acol0+4][arow] = f2tf32(av1.x); As[nb][acol0+5][arow] = f2tf32(av1.y);
            As[nb][acol0+6][arow] = f2tf32(av1.z); As[nb][acol0+7][arow] = f2tf32(av1.w);
            uint4 bu0, bu1;
            bu0.x = f2tf32(bv0.x); bu0.y = f2tf32(bv0.y);
            bu0.z = f2tf32(bv0.z); bu0.w = f2tf32(bv0.w);
            bu1.x = f2tf32(bv1.x); bu1.y = f2tf32(bv1.y);
            bu1.z = f2tf32(bv1.z); bu1.w = f2tf32(bv1.w);
            *(uint4*)&Bs[nb][brow][bcol0]     = bu0;
            *(uint4*)&Bs[nb][brow][bcol0 + 4] = bu1;
            __syncthreads();
            buf = nb;
        }
    }

    #pragma unroll
    for (int mt = 0; mt < 4; mt++) {
        #pragma unroll
        for (int nt = 0; nt < 4; nt++) {
            int r0 = bm + wr + mt*16 + g;
            int c0 = bn + wc + nt*8 + ctg*2;
            #pragma unroll
            for (int rr = 0; rr < 2; rr++) {
                int r = r0 + rr*8;
                #pragma unroll
                for (int cc = 0; cc < 2; cc++) {
                    int c = c0 + cc;
                    float val = acc[mt][nt][rr*2 + cc] + bias[c];
                    if (mode == TEPI_V) {
                        int h = c >> 6, d = c & 63;
                        int b = r / NTOK, n = r % NTOK;
                        out[(((size_t)(b*NH + h)) * NTOK + n) * HD + d] = val;
                    } else {
                        size_t idx = (size_t)r * N + c;
                        if (mode == TEPI_RES)       out[idx] = val + aux[idx];
                        else if (mode == TEPI_GELU) out[idx] = val * normcdff(val);
                        else                        out[idx] += val;   // TEPI_ADD
                    }
                }
            }
        }
    }
}

// ---------------- attention: logits, 64x64 tile, 4x4/thread (exact) --------
__global__ void __launch_bounds__(256) logits_kernel(
    const float* __restrict__ q, const float* __restrict__ k, float* __restrict__ corr) {
    __shared__ float qs[64][68];
    __shared__ float ks[64][68];
    int tid = threadIdx.x;
    int bh = blockIdx.z;
    int m0 = blockIdx.y * 64, n0 = blockIdx.x * 64;
    const float* qb = q + ((size_t)bh * NTOK + m0) * HD;
    const float* kb = k + ((size_t)bh * NTOK + n0) * HD;
    // 64x64 loads, 16 per thread, vectorized float4
    {
        int r = tid >> 2, c4 = (tid & 3) * 16;
        #pragma unroll
        for (int v = 0; v < 4; v++) {
            float4 qv = *(const float4*)(qb + (size_t)r * HD + c4 + v*4);
            float4 kv = *(const float4*)(kb + (size_t)r * HD + c4 + v*4);
            qs[r][c4+v*4+0] = qv.x; qs[r][c4+v*4+1] = qv.y;
            qs[r][c4+v*4+2] = qv.z; qs[r][c4+v*4+3] = qv.w;
            ks[r][c4+v*4+0] = kv.x; ks[r][c4+v*4+1] = kv.y;
            ks[r][c4+v*4+2] = kv.z; ks[r][c4+v*4+3] = kv.w;
        }
    }
    __syncthreads();
    int ty = tid >> 4, tx = tid & 15;   // 16x16 threads, 4x4 outputs each
    float acc[4][4];
    #pragma unroll
    for (int i = 0; i < 4; i++)
        #pragma unroll
        for (int j = 0; j < 4; j++) acc[i][j] = 0.f;
    #pragma unroll
    for (int d = 0; d < 64; d++) {
        float ra[4], rb[4];
        #pragma unroll
        for (int i = 0; i < 4; i++) ra[i] = qs[ty*4 + i][d];
        #pragma unroll
        for (int j = 0; j < 4; j++) rb[j] = ks[tx*4 + j][d];
        #pragma unroll
        for (int i = 0; i < 4; i++)
            #pragma unroll
            for (int j = 0; j < 4; j++)
                acc[i][j] = fmaf(ra[i], rb[j], acc[i][j]);
    }
    float* cb = corr + ((size_t)bh * NTOK + m0 + ty*4) * NTOK + n0 + tx*4;
    #pragma unroll
    for (int i = 0; i < 4; i++)
        #pragma unroll
        for (int j = 0; j < 4; j++)
            cb[(size_t)i * NTOK + j] = acc[i][j] * 0.125f;
}

// ---------------- softmax: warp per row, vec2 lanes ----------------
__global__ void __launch_bounds__(256) softmax_kernel(float* __restrict__ p) {
    int gwarp = (blockIdx.x * blockDim.x + threadIdx.x) >> 5;
    int lane = threadIdx.x & 31;
    float* x = p + (size_t)gwarp * NTOK;

    float v[10];
    #pragma unroll
    for (int i = 0; i < 5; i++) {
        v[2*i]   = x[64*i + 2*lane];
        v[2*i+1] = x[64*i + 2*lane + 1];
    }
    float m = v[0];
    #pragma unroll
    for (int j = 1; j < 10; j++) m = fmaxf(m, v[j]);
    #pragma unroll
    for (int o = 16; o > 0; o >>= 1)
        m = fmaxf(m, __shfl_down_sync(0xffffffffu, m, o));
    m = __shfl_sync(0xffffffffu, m, 0);

    float e[10];
    float a0 = 0.f, a1 = 0.f;
    #pragma unroll
    for (int i = 0; i < 5; i++) {
        e[2*i]   = expf(__fsub_rn(v[2*i],   m));
        e[2*i+1] = expf(__fsub_rn(v[2*i+1], m));
        a0 = __fadd_rn(a0, e[2*i]);
        a1 = __fadd_rn(a1, e[2*i+1]);
    }
    float S = __fadd_rn(a0, a1);
    #pragma unroll
    for (int o = 16; o > 0; o >>= 1)
        S = __fadd_rn(S, __shfl_down_sync(0xffffffffu, S, o));
    S = __shfl_sync(0xffffffffu, S, 0);

    #pragma unroll
    for (int i = 0; i < 5; i++) {
        x[64*i + 2*lane]     = __fdiv_rn(e[2*i],   S);
        x[64*i + 2*lane + 1] = __fdiv_rn(e[2*i+1], S);
    }
}

// ---------------- attention: O = P @ V, 64-row tile, 4x4/thread -------------
__global__ void __launch_bounds__(256) av_kernel(
    const float* __restrict__ corr, const float* __restrict__ v, float* __restrict__ av) {
    __shared__ float Ps[64][33];
    __shared__ float Vs[32][68];
    int tid = threadIdx.x;
    int bh = blockIdx.y;
    int m0 = blockIdx.x * 64;
    int b = bh / NH, h = bh % NH;
    int ty = tid >> 4, tx = tid & 15;
    float acc[4][4];
    #pragma unroll
    for (int i = 0; i < 4; i++)
        #pragma unroll
        for (int j = 0; j < 4; j++) acc[i][j] = 0.f;

    for (int k0 = 0; k0 < NTOK; k0 += 32) {
        // Ps 64x32 = 2048 elems, 8/thread
        {
            int r = tid >> 2, c = (tid & 3) * 8;
            float4 p0 = *(const float4*)&corr[((size_t)bh * NTOK + m0 + r) * NTOK + k0 + c];
            float4 p1 = *(const float4*)&corr[((size_t)bh * NTOK + m0 + r) * NTOK + k0 + c + 4];
            Ps[r][c+0] = p0.x; Ps[r][c+1] = p0.y; Ps[r][c+2] = p0.z; Ps[r][c+3] = p0.w;
            Ps[r][c+4] = p1.x; Ps[r][c+5] = p1.y; Ps[r][c+6] = p1.z; Ps[r][c+7] = p1.w;
        }
        // Vs 32x64 = 2048 elems, 8/thread
        {
            int r = tid >> 3, c = (tid & 7) * 8;
            float4 v0 = *(const float4*)&v[((size_t)bh * NTOK + k0 + r) * HD + c];
            float4 v1 = *(const float4*)&v[((size_t)bh * NTOK + k0 + r) * HD + c + 4];
            Vs[r][c+0] = v0.x; Vs[r][c+1] = v0.y; Vs[r][c+2] = v0.z; Vs[r][c+3] = v0.w;
            Vs[r][c+4] = v1.x; Vs[r][c+5] = v1.y; Vs[r][c+6] = v1.z; Vs[r][c+7] = v1.w;
        }
        __syncthreads();
        #pragma unroll
        for (int kk = 0; kk < 32; kk++) {
            float ra[4], rb[4];
            #pragma unroll
            for (int i = 0; i < 4; i++) ra[i] = Ps[ty*4 + i][kk];
            #pragma unroll
            for (int j = 0; j < 4; j++) rb[j] = Vs[kk][tx*4 + j];
            #pragma unroll
            for (int i = 0; i < 4; i++)
                #pragma unroll
                for (int j = 0; j < 4; j++)
                    acc[i][j] = fmaf(ra[i], rb[j], acc[i][j]);
        }
        __syncthreads();
    }
    #pragma unroll
    for (int i = 0; i < 4; i++) {
        int n = m0 + ty*4 + i;
        float* dst = &av[(((size_t)(b*NTOK + n)) * NH + h) * HD + tx*4];
        #pragma unroll
        for (int j = 0; j < 4; j++) dst[j] = acc[i][j];
    }
}

// ---------------- saliency score: contig-24 chain + tree, recip-mul mean ----
__global__ void score_kernel(const float* __restrict__ cr, const float* __restrict__ ct) {
    int gwarp = (blockIdx.x * blockDim.x + threadIdx.x) >> 5;
    int lane = threadIdx.x & 31;
    int b = gwarp >> 8;
    int s = gwarp & 255;
    float acc = 0.f;
    int i0 = lane * 24;
    #pragma unroll 4
    for (int j = 0; j < 24; j++) {
        int i = i0 + j;
        int h = i >> 6, q = i & 63;
        size_t off = (((size_t)(b*NH + h)) * NTOK + q) * NTOK + NT + s;
        float e = __fadd_rn(cr[off], ct[off]);
        acc = __fadd_rn(acc, e);
    }
    #pragma unroll
    for (int o = 16; o > 0; o >>= 1)
        acc = __fadd_rn(acc, __shfl_down_sync(0xffffffffu, acc, o));
    if (lane == 0) g_score[b*NS + s] = __fmul_rn(acc, (1.0f / 768.0f));
}

// ---------------- stable descending argsort (bitonic 256, fp32 keys) --------
__global__ void sort_kernel(const int* __restrict__ gidx_s,
                            float* __restrict__ out_gs, float* __restrict__ out_rm) {
    __shared__ float sk[256];
    __shared__ int   si[256];
    int b = blockIdx.x, tid = threadIdx.x;
    sk[tid] = g_score[b*NS + tid];
    si[tid] = tid;
    __syncthreads();
    for (int k = 2; k <= 256; k <<= 1) {
        for (int j = k >> 1; j > 0; j >>= 1) {
            int ixj = tid ^ j;
            if (ixj > tid) {
                float ka = sk[tid], kb = sk[ixj];
                int ia = si[tid], ib = si[ixj];
                bool before = (ka > kb) || (ka == kb && ia < ib);
                bool up = ((tid & k) == 0);
                if (up ? !before : before) {
                    sk[tid] = kb; sk[ixj] = ka;
                    si[tid] = ib; si[ixj] = ia;
                }
            }
            __syncthreads();
        }
    }
    int idx = si[tid];
    float gv = (float)gidx_s[b*NS + idx];
    if (tid < NKEEP) {
        out_gs[b*NKEEP + tid] = gv;
        g_topk[b*NKEEP + tid] = idx;
    } else {
        out_rm[b*NREM + (tid - NKEEP)] = gv;
    }
}

// ---------------- copy global_index_t (int -> float) ----------------
__global__ void copy_gt_kernel(const int* __restrict__ gt, float* __restrict__ o) {
    int i = blockIdx.x * 256 + threadIdx.x;
    if (i < BATCH * NT) o[i] = (float)gt[i];
}

// ---------------- token gather (apply keep) ----------------
__global__ void gather_kernel(const float* __restrict__ xres, float* __restrict__ outx) {
    int bt = blockIdx.x;
    int b = bt / NOUT, t = bt % NOUT;
    int src = (t < NT) ? t : NT + g_topk[b*NKEEP + (t - NT)];
    const float* s = xres + ((size_t)(b*NTOK + src)) * DIM;
    float* d = outx + (size_t)bt * DIM;
    for (int c = threadIdx.x; c < DIM; c += 256) d[c] = s[c];
}

// ---------------- launcher ----------------
extern "C" void kernel_launch(void* const* d_in, const int* in_sizes, int n_in,
                              void* d_out, int out_size) {
    const float* x_rgb = (const float*)d_in[0];
    const float* x_tir = (const float*)d_in[1];
    const int*   gt    = (const int*)  d_in[2];
    const int*   gs    = (const int*)  d_in[3];
    const float* n1g = (const float*)d_in[4],  *n1b = (const float*)d_in[5];
    const float* qkvw= (const float*)d_in[6],  *qkvb= (const float*)d_in[7];
    const float* projw=(const float*)d_in[8],  *projb=(const float*)d_in[9];
    const float* n2g = (const float*)d_in[10], *n2b = (const float*)d_in[11];
    const float* fc1w= (const float*)d_in[12], *fc1b= (const float*)d_in[13];
    const float* fc2w= (const float*)d_in[14], *fc2b= (const float*)d_in[15];
    float* out = (float*)d_out;

    float *ln, *q, *k, *v, *av, *xr0, *xr1, *hbuf;
    cudaGetSymbolAddress((void**)&ln,   g_ln);
    cudaGetSymbolAddress((void**)&q,    g_q);
    cudaGetSymbolAddress((void**)&k,    g_k);
    cudaGetSymbolAddress((void**)&v,    g_v);
    cudaGetSymbolAddress((void**)&av,   g_av);
    cudaGetSymbolAddress((void**)&xr0,  g_xres0);
    cudaGetSymbolAddress((void**)&xr1,  g_xres1);
    cudaGetSymbolAddress((void**)&hbuf, g_h);

    float* corr[2]       = { out + OFF_CR, out + OFF_CT };
    const float* xin[2]  = { x_rgb, x_tir };
    float* xres[2]       = { xr0, xr1 };
    float* xout[2]       = { out + OFF_XRGB, out + OFF_XTIR };

    for (int m = 0; m < 2; m++) {
        ln_kernel<<<M1, 256>>>(xin[m], ln, n1g, n1b);
        // exact Q,K (N=1536, ldw=2304)
        sgemm_kernel<<<dim3(1536/128, M1/128), 256>>>(
            ln, qkvw, qkvb, DIM, 2304, q, k);
        // V via TF32 (N=768, ldw=2304, scatter epilogue)
        tf32gemm_kernel<<<dim3(768/128, M1/128), 256>>>(
            ln, qkvw + 1536, qkvb + 1536, M1, 768, DIM, 2304, TEPI_V, v, nullptr);
        logits_kernel<<<dim3(NTOK/64, NTOK/64, BATCH*NH), 256>>>(q, k, corr[m]);
        softmax_kernel<<<(BATCH*NH*NTOK)/8, 256>>>(corr[m]);
        av_kernel<<<dim3(NTOK/64, BATCH*NH), 256>>>(corr[m], v, av);
        tf32gemm_kernel<<<dim3(DIM/128, M1/128), 256>>>(
            av, projw, projb, M1, DIM, DIM, DIM, TEPI_RES, xres[m], xin[m]);
    }

    score_kernel<<<(BATCH*NS*32)/256, 256>>>(corr[0], corr[1]);
    sort_kernel<<<BATCH, 256>>>(gs, out + OFF_GS, out + OFF_RM);
    copy_gt_kernel<<<(BATCH*NT + 255)/256, 256>>>(gt, out + OFF_GT);

    for (int m = 0; m < 2; m++)
        gather_kernel<<<BATCH*NOUT, 256>>>(xres[m], xout[m]);

    for (int m = 0; m < 2; m++) {
        ln_kernel<<<M2, 256>>>(xout[m], ln, n2g, n2b);
        tf32gemm_kernel<<<dim3(MLPH/128, M2/128), 256>>>(
            ln, fc1w, fc1b, M2, MLPH, DIM, MLPH, TEPI_GELU, hbuf, nullptr);
        tf32gemm_kernel<<<dim3(DIM/128, M2/128), 256>>>(
            hbuf, fc2w, fc2b, M2, DIM, MLPH, DIM, TEPI_ADD, xout[m], nullptr);
    }
}

// round 15
// speedup vs baseline: 2.3698x; 1.0926x over previous
#include <cuda_runtime.h>
#include <math.h>
#include <stdint.h>

// ---------------- problem constants ----------------
#define BATCH 64
#define NTOK  320
#define NT    64
#define NS    256
#define DIM   768
#define NH    12
#define HD    64
#define MLPH  3072
#define NKEEP 180
#define NREM  76
#define NOUT  244
#define M1    (BATCH*NTOK)   // 20480
#define M2    (BATCH*NOUT)   // 15616

// output layout (flat float32)
#define OFF_XRGB 0LL
#define OFF_XTIR 11993088LL
#define OFF_GT   23986176LL
#define OFF_GS   23990272LL
#define OFF_RM   24001792LL
#define OFF_CR   24006656LL
#define OFF_CT   102649856LL

// ---------------- device scratch ----------------
__device__ float g_ln[(size_t)M1*DIM];
__device__ float g_q [(size_t)BATCH*NH*NTOK*HD];
__device__ float g_k [(size_t)BATCH*NH*NTOK*HD];
__device__ float g_v [(size_t)BATCH*NH*NTOK*HD];
__device__ float g_av[(size_t)M1*DIM];
__device__ float g_xres0[(size_t)M1*DIM];
__device__ float g_xres1[(size_t)M1*DIM];
__device__ float g_h [(size_t)M2*MLPH];
__device__ float g_score[BATCH*NS];
__device__ int   g_topk[BATCH*NKEEP];

// ---------------- reductions ----------------
__device__ __forceinline__ float block_sum(float v, float* red) {
    #pragma unroll
    for (int o = 16; o > 0; o >>= 1) v += __shfl_xor_sync(0xffffffffu, v, o);
    int tid = threadIdx.x;
    if ((tid & 31) == 0) red[tid >> 5] = v;
    __syncthreads();
    if (tid < 32) {
        float t = (tid < 8) ? red[tid] : 0.f;
        #pragma unroll
        for (int o = 4; o > 0; o >>= 1) t += __shfl_xor_sync(0xffffffffu, t, o);
        if (tid == 0) red[0] = t;
    }
    __syncthreads();
    float r = red[0];
    __syncthreads();
    return r;
}

// ---------------- LayerNorm (row = token of 768), block tree ----------------
__global__ void ln_kernel(const float* __restrict__ in, float* __restrict__ out,
                          const float* __restrict__ gam, const float* __restrict__ bet) {
    __shared__ float red[32];
    size_t row = blockIdx.x;
    const float* x = in + row * DIM;
    float* o = out + row * DIM;
    int tid = threadIdx.x;           // 256
    float lv[3];
    float s = 0.f;
    #pragma unroll
    for (int i = 0; i < 3; i++) { lv[i] = x[tid + i*256]; s += lv[i]; }
    float mean = block_sum(s, red) * (1.0f / DIM);
    float vs = 0.f;
    #pragma unroll
    for (int i = 0; i < 3; i++) { float d = lv[i] - mean; vs += d * d; }
    float var = block_sum(vs, red) * (1.0f / DIM);
    float rstd = rsqrtf(var + 1e-5f);
    #pragma unroll
    for (int i = 0; i < 3; i++) {
        int c = tid + i*256;
        o[c] = (lv[i] - mean) * rstd * gam[c] + bet[c];
    }
}

// ---------------- exact fp32 SGEMM, double-buffered K16 (Q,K only) ---------
__global__ void __launch_bounds__(256) sgemm_kernel(
    const float* __restrict__ A, const float* __restrict__ W,
    const float* __restrict__ bias, int K, int ldw,
    float* __restrict__ qp, float* __restrict__ kp) {

    __shared__ float As[2][16][128];
    __shared__ float Bs[2][16][128];
    int tid = threadIdx.x;
    int bm = blockIdx.y * 128, bn = blockIdx.x * 128;
    int ty = tid >> 4, tx = tid & 15;

    float acc[8][8];
    #pragma unroll
    for (int i = 0; i < 8; i++)
        #pragma unroll
        for (int j = 0; j < 8; j++) acc[i][j] = 0.f;

    int arow = tid >> 1, acol = (tid & 1) * 8;
    int brow = tid >> 4, bcol = (tid & 15) * 8;
    const float* Aptr = A + (size_t)(bm + arow) * K + acol;
    const float* Wptr = W + (size_t)brow * ldw + bn + bcol;

    float4 a0 = *(const float4*)(Aptr);
    float4 a1 = *(const float4*)(Aptr + 4);
    float4 b0 = *(const float4*)(Wptr);
    float4 b1 = *(const float4*)(Wptr + 4);
    As[0][acol+0][arow] = a0.x; As[0][acol+1][arow] = a0.y;
    As[0][acol+2][arow] = a0.z; As[0][acol+3][arow] = a0.w;
    As[0][acol+4][arow] = a1.x; As[0][acol+5][arow] = a1.y;
    As[0][acol+6][arow] = a1.z; As[0][acol+7][arow] = a1.w;
    *(float4*)&Bs[0][brow][bcol]     = b0;
    *(float4*)&Bs[0][brow][bcol + 4] = b1;
    __syncthreads();

    int buf = 0;
    for (int k0 = 16; k0 <= K; k0 += 16) {
        if (k0 < K) {
            a0 = *(const float4*)(Aptr + k0);
            a1 = *(const float4*)(Aptr + k0 + 4);
            b0 = *(const float4*)(Wptr + (size_t)k0 * ldw);
            b1 = *(const float4*)(Wptr + (size_t)k0 * ldw + 4);
        }
        #pragma unroll
        for (int kk = 0; kk < 16; kk++) {
            float ra[8], rb[8];
            #pragma unroll
            for (int i = 0; i < 8; i++) ra[i] = As[buf][kk][ty*8 + i];
            #pragma unroll
            for (int j = 0; j < 8; j++) rb[j] = Bs[buf][kk][tx*8 + j];
            #pragma unroll
            for (int i = 0; i < 8; i++)
                #pragma unroll
                for (int j = 0; j < 8; j++)
                    acc[i][j] = fmaf(ra[i], rb[j], acc[i][j]);
        }
        if (k0 < K) {
            int nb = buf ^ 1;
            As[nb][acol+0][arow] = a0.x; As[nb][acol+1][arow] = a0.y;
            As[nb][acol+2][arow] = a0.z; As[nb][acol+3][arow] = a0.w;
            As[nb][acol+4][arow] = a1.x; As[nb][acol+5][arow] = a1.y;
            As[nb][acol+6][arow] = a1.z; As[nb][acol+7][arow] = a1.w;
            *(float4*)&Bs[nb][brow][bcol]     = b0;
            *(float4*)&Bs[nb][brow][bcol + 4] = b1;
            __syncthreads();
            buf = nb;
        }
    }

    #pragma unroll
    for (int i = 0; i < 8; i++) {
        int r = bm + ty*8 + i;
        #pragma unroll
        for (int j = 0; j < 8; j++) {
            int c = bn + tx*8 + j;          // c in [0,1536)
            float val = acc[i][j] + bias[c];
            int which = c / 768;            // 0 = q, 1 = k
            int h = (c % 768) >> 6;
            int d = c & 63;
            int b = r / NTOK, n = r % NTOK;
            size_t dst = (((size_t)(b*NH + h)) * NTOK + n) * HD + d;
            float* base = (which == 0) ? qp : kp;
            base[dst] = val;
        }
    }
}

// ---------------- TF32 tensor-core GEMM (proj / fc1 / fc2 / V) --------------
#define TEPI_RES  1
#define TEPI_GELU 2
#define TEPI_ADD  3
#define TEPI_V    4
#define SPAD 8

__device__ __forceinline__ uint32_t f2tf32(float f) {
    uint32_t r;
    asm("cvt.rna.tf32.f32 %0, %1;" : "=r"(r) : "f"(f));
    return r;
}

__device__ __forceinline__ void mma_tf32(float* c, const uint32_t* a, const uint32_t* b) {
    asm volatile(
        "mma.sync.aligned.m16n8k8.row.col.f32.tf32.tf32.f32 "
        "{%0,%1,%2,%3}, {%4,%5,%6,%7}, {%8,%9}, {%0,%1,%2,%3};"
        : "+f"(c[0]), "+f"(c[1]), "+f"(c[2]), "+f"(c[3])
        : "r"(a[0]), "r"(a[1]), "r"(a[2]), "r"(a[3]), "r"(b[0]), "r"(b[1]));
}

__global__ void __launch_bounds__(256) tf32gemm_kernel(
    const float* __restrict__ A, const float* __restrict__ W,
    const float* __restrict__ bias, int M, int N, int K, int ldw, int mode,
    float* __restrict__ out, const float* __restrict__ aux) {

    __shared__ uint32_t As[2][16][128 + SPAD];
    __shared__ uint32_t Bs[2][16][128 + SPAD];

    int tid = threadIdx.x;
    int bm = blockIdx.y * 128, bn = blockIdx.x * 128;
    int warp = tid >> 5, lane = tid & 31;
    int g = lane >> 2, ctg = lane & 3;
    int wr = (warp >> 2) * 64;
    int wc = (warp & 3) * 32;

    float acc[4][4][4];
    #pragma unroll
    for (int mt = 0; mt < 4; mt++)
        #pragma unroll
        for (int nt = 0; nt < 4; nt++)
            #pragma unroll
            for (int r = 0; r < 4; r++) acc[mt][nt][r] = 0.f;

    int arow = tid >> 1, acol0 = (tid & 1) * 8;
    int brow = tid >> 4, bcol0 = (tid & 15) * 8;
    const float* Ap = A + (size_t)(bm + arow) * K;
    const float* Wp = W + bn;

    float4 av0 = *(const float4*)(Ap + acol0);
    float4 av1 = *(const float4*)(Ap + acol0 + 4);
    float4 bv0 = *(const float4*)(Wp + (size_t)brow * ldw + bcol0);
    float4 bv1 = *(const float4*)(Wp + (size_t)brow * ldw + bcol0 + 4);

    {
        As[0][acol0+0][arow] = f2tf32(av0.x); As[0][acol0+1][arow] = f2tf32(av0.y);
        As[0][acol0+2][arow] = f2tf32(av0.z); As[0][acol0+3][arow] = f2tf32(av0.w);
        As[0][acol0+4][arow] = f2tf32(av1.x); As[0][acol0+5][arow] = f2tf32(av1.y);
        As[0][acol0+6][arow] = f2tf32(av1.z); As[0][acol0+7][arow] = f2tf32(av1.w);
        uint4 bu0, bu1;
        bu0.x = f2tf32(bv0.x); bu0.y = f2tf32(bv0.y);
        bu0.z = f2tf32(bv0.z); bu0.w = f2tf32(bv0.w);
        bu1.x = f2tf32(bv1.x); bu1.y = f2tf32(bv1.y);
        bu1.z = f2tf32(bv1.z); bu1.w = f2tf32(bv1.w);
        *(uint4*)&Bs[0][brow][bcol0]     = bu0;
        *(uint4*)&Bs[0][brow][bcol0 + 4] = bu1;
    }
    __syncthreads();

    int buf = 0;
    for (int k0 = 16; k0 <= K; k0 += 16) {
        if (k0 < K) {
            av0 = *(const float4*)(Ap + k0 + acol0);
            av1 = *(const float4*)(Ap + k0 + acol0 + 4);
            bv0 = *(const float4*)(Wp + (size_t)(k0 + brow) * ldw + bcol0);
            bv1 = *(const float4*)(Wp + (size_t)(k0 + brow) * ldw + bcol0 + 4);
        }
        #pragma unroll
        for (int ks = 0; ks < 16; ks += 8) {
            uint32_t af[4][4];
            #pragma unroll
            for (int mt = 0; mt < 4; mt++) {
                int m0 = wr + mt*16 + g;
                af[mt][0] = As[buf][ks+ctg  ][m0];
                af[mt][1] = As[buf][ks+ctg  ][m0+8];
                af[mt][2] = As[buf][ks+ctg+4][m0];
                af[mt][3] = As[buf][ks+ctg+4][m0+8];
            }
            uint32_t bf[4][2];
            #pragma unroll
            for (int nt = 0; nt < 4; nt++) {
                int n0 = wc + nt*8 + g;
                bf[nt][0] = Bs[buf][ks+ctg  ][n0];
                bf[nt][1] = Bs[buf][ks+ctg+4][n0];
            }
            #pragma unroll
            for (int mt = 0; mt < 4; mt++)
                #pragma unroll
                for (int nt = 0; nt < 4; nt++)
                    mma_tf32(acc[mt][nt], af[mt], bf[nt]);
        }
        if (k0 < K) {
            int nb = buf ^ 1;
            As[nb][acol0+0][arow] = f2tf32(av0.x); As[nb][acol0+1][arow] = f2tf32(av0.y);
            As[nb][acol0+2][arow] = f2tf32(av0.z); As[nb][acol0+3][arow] = f2tf32(av0.w);
            As[nb][acol0+4][arow] = f2tf32(av1.x); As[nb][acol0+5][arow] = f2tf32(av1.y);
            As[nb][acol0+6][arow] = f2tf32(av1.z); As[nb][acol0+7][arow] = f2tf32(av1.w);
            uint4 bu0, bu1;
            bu0.x = f2tf32(bv0.x); bu0.y = f2tf32(bv0.y);
            bu0.z = f2tf32(bv0.z); bu0.w = f2tf32(bv0.w);
            bu1.x = f2tf32(bv1.x); bu1.y = f2tf32(bv1.y);
            bu1.z = f2tf32(bv1.z); bu1.w = f2tf32(bv1.w);
            *(uint4*)&Bs[nb][brow][bcol0]     = bu0;
            *(uint4*)&Bs[nb][brow][bcol0 + 4] = bu1;
            __syncthreads();
            buf = nb;
        }
    }

    #pragma unroll
    for (int mt = 0; mt < 4; mt++) {
        #pragma unroll
        for (int nt = 0; nt < 4; nt++) {
            int r0 = bm + wr + mt*16 + g;
            int c0 = bn + wc + nt*8 + ctg*2;
            #pragma unroll
            for (int rr = 0; rr < 2; rr++) {
                int r = r0 + rr*8;
                #pragma unroll
                for (int cc = 0; cc < 2; cc++) {
                    int c = c0 + cc;
                    float val = acc[mt][nt][rr*2 + cc] + bias[c];
                    if (mode == TEPI_V) {
                        int h = c >> 6, d = c & 63;
                        int b = r / NTOK, n = r % NTOK;
                        out[(((size_t)(b*NH + h)) * NTOK + n) * HD + d] = val;
                    } else {
                        size_t idx = (size_t)r * N + c;
                        if (mode == TEPI_RES)       out[idx] = val + aux[idx];
                        else if (mode == TEPI_GELU) out[idx] = val * normcdff(val);
                        else                        out[idx] += val;   // TEPI_ADD
                    }
                }
            }
        }
    }
}

// ---------------- attention: logits, 64x64, conflict-free smem (exact) -----
// K tile stored transposed (ks_t[d][col]) so the B fragment is one float4
// LDS.128 per d-step: banks distinct per quarter-warp. Per-output FMA chain
// remains d-ascending single-accumulator -> corr bitwise unchanged.
__global__ void __launch_bounds__(256) logits_kernel(
    const float* __restrict__ q, const float* __restrict__ k, float* __restrict__ corr) {
    __shared__ float qs[64][68];
    __shared__ float ks_t[64][68];   // [d][col]
    int tid = threadIdx.x;
    int bh = blockIdx.z;
    int m0 = blockIdx.y * 64, n0 = blockIdx.x * 64;
    const float* qb = q + ((size_t)bh * NTOK + m0) * HD;
    const float* kb = k + ((size_t)bh * NTOK + n0) * HD;
    {
        int r = tid >> 2, c4 = (tid & 3) * 16;
        #pragma unroll
        for (int v = 0; v < 4; v++) {
            float4 qv = *(const float4*)(qb + (size_t)r * HD + c4 + v*4);
            float4 kv = *(const float4*)(kb + (size_t)r * HD + c4 + v*4);
            qs[r][c4+v*4+0] = qv.x; qs[r][c4+v*4+1] = qv.y;
            qs[r][c4+v*4+2] = qv.z; qs[r][c4+v*4+3] = qv.w;
            ks_t[c4+v*4+0][r] = kv.x; ks_t[c4+v*4+1][r] = kv.y;
            ks_t[c4+v*4+2][r] = kv.z; ks_t[c4+v*4+3][r] = kv.w;
        }
    }
    __syncthreads();
    int ty = tid >> 4, tx = tid & 15;
    float acc[4][4];
    #pragma unroll
    for (int i = 0; i < 4; i++)
        #pragma unroll
        for (int j = 0; j < 4; j++) acc[i][j] = 0.f;
    #pragma unroll
    for (int d = 0; d < 64; d++) {
        float4 rb4 = *(const float4*)&ks_t[d][tx*4];
        float rb[4] = { rb4.x, rb4.y, rb4.z, rb4.w };
        float ra[4];
        #pragma unroll
        for (int i = 0; i < 4; i++) ra[i] = qs[ty*4 + i][d];
        #pragma unroll
        for (int i = 0; i < 4; i++)
            #pragma unroll
            for (int j = 0; j < 4; j++)
                acc[i][j] = fmaf(ra[i], rb[j], acc[i][j]);
    }
    float* cb = corr + ((size_t)bh * NTOK + m0 + ty*4) * NTOK + n0 + tx*4;
    #pragma unroll
    for (int i = 0; i < 4; i++)
        #pragma unroll
        for (int j = 0; j < 4; j++)
            cb[(size_t)i * NTOK + j] = acc[i][j] * 0.125f;
}

// ---------------- softmax: warp per row, vec2 lanes ----------------
__global__ void __launch_bounds__(256) softmax_kernel(float* __restrict__ p) {
    int gwarp = (blockIdx.x * blockDim.x + threadIdx.x) >> 5;
    int lane = threadIdx.x & 31;
    float* x = p + (size_t)gwarp * NTOK;

    float v[10];
    #pragma unroll
    for (int i = 0; i < 5; i++) {
        v[2*i]   = x[64*i + 2*lane];
        v[2*i+1] = x[64*i + 2*lane + 1];
    }
    float m = v[0];
    #pragma unroll
    for (int j = 1; j < 10; j++) m = fmaxf(m, v[j]);
    #pragma unroll
    for (int o = 16; o > 0; o >>= 1)
        m = fmaxf(m, __shfl_down_sync(0xffffffffu, m, o));
    m = __shfl_sync(0xffffffffu, m, 0);

    float e[10];
    float a0 = 0.f, a1 = 0.f;
    #pragma unroll
    for (int i = 0; i < 5; i++) {
        e[2*i]   = expf(__fsub_rn(v[2*i],   m));
        e[2*i+1] = expf(__fsub_rn(v[2*i+1], m));
        a0 = __fadd_rn(a0, e[2*i]);
        a1 = __fadd_rn(a1, e[2*i+1]);
    }
    float S = __fadd_rn(a0, a1);
    #pragma unroll
    for (int o = 16; o > 0; o >>= 1)
        S = __fadd_rn(S, __shfl_down_sync(0xffffffffu, S, o));
    S = __shfl_sync(0xffffffffu, S, 0);

    #pragma unroll
    for (int i = 0; i < 5; i++) {
        x[64*i + 2*lane]     = __fdiv_rn(e[2*i],   S);
        x[64*i + 2*lane + 1] = __fdiv_rn(e[2*i+1], S);
    }
}

// ---------------- attention: O = P @ V, 64-row tile, 4x4/thread -------------
__global__ void __launch_bounds__(256) av_kernel(
    const float* __restrict__ corr, const float* __restrict__ v, float* __restrict__ av) {
    __shared__ float Ps[64][33];
    __shared__ float Vs[32][68];
    int tid = threadIdx.x;
    int bh = blockIdx.y;
    int m0 = blockIdx.x * 64;
    int b = bh / NH, h = bh % NH;
    int ty = tid >> 4, tx = tid & 15;
    float acc[4][4];
    #pragma unroll
    for (int i = 0; i < 4; i++)
        #pragma unroll
        for (int j = 0; j < 4; j++) acc[i][j] = 0.f;

    for (int k0 = 0; k0 < NTOK; k0 += 32) {
        {
            int r = tid >> 2, c = (tid & 3) * 8;
            float4 p0 = *(const float4*)&corr[((size_t)bh * NTOK + m0 + r) * NTOK + k0 + c];
            float4 p1 = *(const float4*)&corr[((size_t)bh * NTOK + m0 + r) * NTOK + k0 + c + 4];
            Ps[r][c+0] = p0.x; Ps[r][c+1] = p0.y; Ps[r][c+2] = p0.z; Ps[r][c+3] = p0.w;
            Ps[r][c+4] = p1.x; Ps[r][c+5] = p1.y; Ps[r][c+6] = p1.z; Ps[r][c+7] = p1.w;
        }
        {
            int r = tid >> 3, c = (tid & 7) * 8;
            float4 v0 = *(const float4*)&v[((size_t)bh * NTOK + k0 + r) * HD + c];
            float4 v1 = *(const float4*)&v[((size_t)bh * NTOK + k0 + r) * HD + c + 4];
            Vs[r][c+0] = v0.x; Vs[r][c+1] = v0.y; Vs[r][c+2] = v0.z; Vs[r][c+3] = v0.w;
            Vs[r][c+4] = v1.x; Vs[r][c+5] = v1.y; Vs[r][c+6] = v1.z; Vs[r][c+7] = v1.w;
        }
        __syncthreads();
        #pragma unroll
        for (int kk = 0; kk < 32; kk++) {
            float4 rb4 = *(const float4*)&Vs[kk][tx*4];
            float rb[4] = { rb4.x, rb4.y, rb4.z, rb4.w };
            float ra[4];
            #pragma unroll
            for (int i = 0; i < 4; i++) ra[i] = Ps[ty*4 + i][kk];
            #pragma unroll
            for (int i = 0; i < 4; i++)
                #pragma unroll
                for (int j = 0; j < 4; j++)
                    acc[i][j] = fmaf(ra[i], rb[j], acc[i][j]);
        }
        __syncthreads();
    }
    #pragma unroll
    for (int i = 0; i < 4; i++) {
        int n = m0 + ty*4 + i;
        float* dst = &av[(((size_t)(b*NTOK + n)) * NH + h) * HD + tx*4];
        #pragma unroll
        for (int j = 0; j < 4; j++) dst[j] = acc[i][j];
    }
}

// ---------------- saliency score: contig-24 chain + tree, recip-mul mean ----
__global__ void score_kernel(const float* __restrict__ cr, const float* __restrict__ ct) {
    int gwarp = (blockIdx.x * blockDim.x + threadIdx.x) >> 5;
    int lane = threadIdx.x & 31;
    int b = gwarp >> 8;
    int s = gwarp & 255;
    float acc = 0.f;
    int i0 = lane * 24;
    #pragma unroll 4
    for (int j = 0; j < 24; j++) {
        int i = i0 + j;
        int h = i >> 6, q = i & 63;
        size_t off = (((size_t)(b*NH + h)) * NTOK + q) * NTOK + NT + s;
        float e = __fadd_rn(cr[off], ct[off]);
        acc = __fadd_rn(acc, e);
    }
    #pragma unroll
    for (int o = 16; o > 0; o >>= 1)
        acc = __fadd_rn(acc, __shfl_down_sync(0xffffffffu, acc, o));
    if (lane == 0) g_score[b*NS + s] = __fmul_rn(acc, (1.0f / 768.0f));
}

// ---------------- stable descending argsort (bitonic 256, fp32 keys) --------
__global__ void sort_kernel(const int* __restrict__ gidx_s,
                            float* __restrict__ out_gs, float* __restrict__ out_rm) {
    __shared__ float sk[256];
    __shared__ int   si[256];
    int b = blockIdx.x, tid = threadIdx.x;
    sk[tid] = g_score[b*NS + tid];
    si[tid] = tid;
    __syncthreads();
    for (int k = 2; k <= 256; k <<= 1) {
        for (int j = k >> 1; j > 0; j >>= 1) {
            int ixj = tid ^ j;
            if (ixj > tid) {
                float ka = sk[tid], kb = sk[ixj];
                int ia = si[tid], ib = si[ixj];
                bool before = (ka > kb) || (ka == kb && ia < ib);
                bool up = ((tid & k) == 0);
                if (up ? !before : before) {
                    sk[tid] = kb; sk[ixj] = ka;
                    si[tid] = ib; si[ixj] = ia;
                }
            }
            __syncthreads();
        }
    }
    int idx = si[tid];
    float gv = (float)gidx_s[b*NS + idx];
    if (tid < NKEEP) {
        out_gs[b*NKEEP + tid] = gv;
        g_topk[b*NKEEP + tid] = idx;
    } else {
        out_rm[b*NREM + (tid - NKEEP)] = gv;
    }
}

// ---------------- copy global_index_t (int -> float) ----------------
__global__ void copy_gt_kernel(const int* __restrict__ gt, float* __restrict__ o) {
    int i = blockIdx.x * 256 + threadIdx.x;
    if (i < BATCH * NT) o[i] = (float)gt[i];
}

// ---------------- token gather (apply keep) ----------------
__global__ void gather_kernel(const float* __restrict__ xres, float* __restrict__ outx) {
    int bt = blockIdx.x;
    int b = bt / NOUT, t = bt % NOUT;
    int src = (t < NT) ? t : NT + g_topk[b*NKEEP + (t - NT)];
    const float* s = xres + ((size_t)(b*NTOK + src)) * DIM;
    float* d = outx + (size_t)bt * DIM;
    for (int c = threadIdx.x; c < DIM; c += 256) d[c] = s[c];
}

// ---------------- launcher ----------------
extern "C" void kernel_launch(void* const* d_in, const int* in_sizes, int n_in,
                              void* d_out, int out_size) {
    const float* x_rgb = (const float*)d_in[0];
    const float* x_tir = (const float*)d_in[1];
    const int*   gt    = (const int*)  d_in[2];
    const int*   gs    = (const int*)  d_in[3];
    const float* n1g = (const float*)d_in[4],  *n1b = (const float*)d_in[5];
    const float* qkvw= (const float*)d_in[6],  *qkvb= (const float*)d_in[7];
    const float* projw=(const float*)d_in[8],  *projb=(const float*)d_in[9];
    const float* n2g = (const float*)d_in[10], *n2b = (const float*)d_in[11];
    const float* fc1w= (const float*)d_in[12], *fc1b= (const float*)d_in[13];
    const float* fc2w= (const float*)d_in[14], *fc2b= (const float*)d_in[15];
    float* out = (float*)d_out;

    float *ln, *q, *k, *v, *av, *xr0, *xr1, *hbuf;
    cudaGetSymbolAddress((void**)&ln,   g_ln);
    cudaGetSymbolAddress((void**)&q,    g_q);
    cudaGetSymbolAddress((void**)&k,    g_k);
    cudaGetSymbolAddress((void**)&v,    g_v);
    cudaGetSymbolAddress((void**)&av,   g_av);
    cudaGetSymbolAddress((void**)&xr0,  g_xres0);
    cudaGetSymbolAddress((void**)&xr1,  g_xres1);
    cudaGetSymbolAddress((void**)&hbuf, g_h);

    float* corr[2]       = { out + OFF_CR, out + OFF_CT };
    const float* xin[2]  = { x_rgb, x_tir };
    float* xres[2]       = { xr0, xr1 };
    float* xout[2]       = { out + OFF_XRGB, out + OFF_XTIR };

    for (int m = 0; m < 2; m++) {
        ln_kernel<<<M1, 256>>>(xin[m], ln, n1g, n1b);
        sgemm_kernel<<<dim3(1536/128, M1/128), 256>>>(
            ln, qkvw, qkvb, DIM, 2304, q, k);
        tf32gemm_kernel<<<dim3(768/128, M1/128), 256>>>(
            ln, qkvw + 1536, qkvb + 1536, M1, 768, DIM, 2304, TEPI_V, v, nullptr);
        logits_kernel<<<dim3(NTOK/64, NTOK/64, BATCH*NH), 256>>>(q, k, corr[m]);
        softmax_kernel<<<(BATCH*NH*NTOK)/8, 256>>>(corr[m]);
        av_kernel<<<dim3(NTOK/64, BATCH*NH), 256>>>(corr[m], v, av);
        tf32gemm_kernel<<<dim3(DIM/128, M1/128), 256>>>(
            av, projw, projb, M1, DIM, DIM, DIM, TEPI_RES, xres[m], xin[m]);
    }

    score_kernel<<<(BATCH*NS*32)/256, 256>>>(corr[0], corr[1]);
    sort_kernel<<<BATCH, 256>>>(gs, out + OFF_GS, out + OFF_RM);
    copy_gt_kernel<<<(BATCH*NT + 255)/256, 256>>>(gt, out + OFF_GT);

    for (int m = 0; m < 2; m++)
        gather_kernel<<<BATCH*NOUT, 256>>>(xres[m], xout[m]);

    for (int m = 0; m < 2; m++) {
        ln_kernel<<<M2, 256>>>(xout[m], ln, n2g, n2b);
        tf32gemm_kernel<<<dim3(MLPH/128, M2/128), 256>>>(
            ln, fc1w, fc1b, M2, MLPH, DIM, MLPH, TEPI_GELU, hbuf, nullptr);
        tf32gemm_kernel<<<dim3(DIM/128, M2/128), 256>>>(
            hbuf, fc2w, fc2b, M2, DIM, MLPH, DIM, TEPI_ADD, xout[m], nullptr);
    }
}